// round 1
// baseline (speedup 1.0000x reference)
#include <cuda_runtime.h>
#include <cuda_bf16.h>
#include <cstddef>

// ---------------- problem dims ----------------
#define WORDN 30000
#define NGRAMN 50000
#define FDIM  80000
#define Bz 32
#define Lz 64
#define Tz (Bz*Lz)          // 2048 tokens
#define Kz 6
#define Dz 256
#define Hz 8
#define HDz 32
#define FFDz 512
#define DFFz 1024
#define NLz 2
#define EPSz 1e-5f

// ---------------- scratch (no allocation allowed) ----------------
__device__ float g_h0[Tz * FFDz];     // 4 MB
__device__ float g_x[Tz * Dz];        // 2 MB
__device__ float g_qkv[Tz * 3 * Dz];  // 6 MB
__device__ float g_attno[Tz * Dz];
__device__ float g_obuf[Tz * Dz];
__device__ float g_f1[Tz * DFFz];     // 8 MB
__device__ float g_f2[Tz * Dz];

// ---------------- embed: gather columns of fc1_w, +bias, relu ----------------
__global__ __launch_bounds__(512) void embed_kernel(
    const int* __restrict__ word, const int* __restrict__ ngram,
    const float* __restrict__ fc1w, const float* __restrict__ fc1b,
    float* __restrict__ h0)
{
    int t = blockIdx.x;
    __shared__ int cols[7];
    __shared__ int ncols_s;
    if (threadIdx.x == 0) {
        int n = 0;
        cols[n++] = word[t];
        for (int k = 0; k < Kz; k++) {
            int c = WORDN + ngram[t * Kz + k];
            bool dup = false;
            for (int j = 1; j < n; j++) if (cols[j] == c) dup = true;
            if (!dup) cols[n++] = c;
        }
        ncols_s = n;
    }
    __syncthreads();
    int r = threadIdx.x;          // 0..511
    int n = ncols_s;
    const float* row = fc1w + (size_t)r * FDIM;
    float s = fc1b[r];
    for (int i = 0; i < n; i++) s += __ldg(row + cols[i]);
    h0[(size_t)t * FFDz + r] = fmaxf(s, 0.0f);
}

// ---------------- generic GEMM: C[M,N] = A[M,K] @ W[N,K]^T + bias (opt relu) --
// BM=BN=64, BK=16, 256 threads, 4x4 per-thread microtile. M%64==0, N%64==0, K%16==0.
template<bool RELU>
__global__ __launch_bounds__(256) void gemm_kernel(
    const float* __restrict__ A, const float* __restrict__ W,
    const float* __restrict__ bias, float* __restrict__ C,
    int M, int N, int K)
{
    __shared__ __align__(16) float As[16][64];
    __shared__ __align__(16) float Ws[16][64];
    int tid = threadIdx.x;
    int row0 = blockIdx.y * 64;
    int col0 = blockIdx.x * 64;
    int lm = tid >> 2;           // 0..63
    int lk = (tid & 3) * 4;      // 0,4,8,12
    int ty = tid >> 4;           // 0..15
    int tx = tid & 15;           // 0..15

    float acc[4][4] = {};

    const float* Ap = A + (size_t)(row0 + lm) * K + lk;
    const float* Wp = W + (size_t)(col0 + lm) * K + lk;

    for (int kt = 0; kt < K; kt += 16) {
        float4 av = *(const float4*)(Ap + kt);
        float4 wv = *(const float4*)(Wp + kt);
        As[lk + 0][lm] = av.x; As[lk + 1][lm] = av.y;
        As[lk + 2][lm] = av.z; As[lk + 3][lm] = av.w;
        Ws[lk + 0][lm] = wv.x; Ws[lk + 1][lm] = wv.y;
        Ws[lk + 2][lm] = wv.z; Ws[lk + 3][lm] = wv.w;
        __syncthreads();
        #pragma unroll
        for (int kk = 0; kk < 16; kk++) {
            float4 a = *(const float4*)&As[kk][ty * 4];
            float4 w = *(const float4*)&Ws[kk][tx * 4];
            float ar[4] = {a.x, a.y, a.z, a.w};
            float wr[4] = {w.x, w.y, w.z, w.w};
            #pragma unroll
            for (int i = 0; i < 4; i++)
                #pragma unroll
                for (int j = 0; j < 4; j++)
                    acc[i][j] += ar[i] * wr[j];
        }
        __syncthreads();
    }

    float4 bv = *(const float4*)(bias + col0 + tx * 4);
    float br[4] = {bv.x, bv.y, bv.z, bv.w};
    #pragma unroll
    for (int i = 0; i < 4; i++) {
        int r = row0 + ty * 4 + i;
        float4 o;
        o.x = acc[i][0] + br[0];
        o.y = acc[i][1] + br[1];
        o.z = acc[i][2] + br[2];
        o.w = acc[i][3] + br[3];
        if (RELU) {
            o.x = fmaxf(o.x, 0.f); o.y = fmaxf(o.y, 0.f);
            o.z = fmaxf(o.z, 0.f); o.w = fmaxf(o.w, 0.f);
        }
        *(float4*)(C + (size_t)r * N + col0 + tx * 4) = o;
    }
}

// ---------------- attention: one block per (b,h), L=64, hd=32 ----------------
__global__ __launch_bounds__(128) void attn_kernel(
    const float* __restrict__ qkv, float* __restrict__ out)
{
    int bh = blockIdx.x;
    int b = bh >> 3, h = bh & 7;
    __shared__ float Q[64][33], Ksm[64][33], V[64][33];
    __shared__ float S[64][65];
    int tid = threadIdx.x;
    const float scale = 0.17677669529663687f;  // 1/sqrt(32)

    for (int idx = tid; idx < 64 * 32; idx += 128) {
        int l = idx >> 5, j = idx & 31;
        size_t base = (size_t)(b * 64 + l) * (3 * Dz) + h * 32 + j;
        Q[l][j]   = qkv[base];
        Ksm[l][j] = qkv[base + Dz];
        V[l][j]   = qkv[base + 2 * Dz];
    }
    __syncthreads();

    for (int idx = tid; idx < 64 * 64; idx += 128) {
        int i = idx >> 6, j = idx & 63;
        float s = 0.f;
        #pragma unroll
        for (int d = 0; d < 32; d++) s += Q[i][d] * Ksm[j][d];
        S[i][j] = s * scale;
    }
    __syncthreads();

    if (tid < 64) {
        int i = tid;
        float m = -1e30f;
        #pragma unroll 8
        for (int j = 0; j < 64; j++) m = fmaxf(m, S[i][j]);
        float sum = 0.f;
        #pragma unroll 8
        for (int j = 0; j < 64; j++) { float e = __expf(S[i][j] - m); S[i][j] = e; sum += e; }
        float inv = 1.f / sum;
        #pragma unroll 8
        for (int j = 0; j < 64; j++) S[i][j] *= inv;
    }
    __syncthreads();

    for (int idx = tid; idx < 64 * 32; idx += 128) {
        int i = idx >> 5, d = idx & 31;
        float s = 0.f;
        #pragma unroll
        for (int j = 0; j < 64; j++) s += S[i][j] * V[j][d];
        out[(size_t)(b * 64 + i) * Dz + h * 32 + d] = s;
    }
}

// ---------------- residual add + layernorm: one block (256 thr) per token -----
__global__ __launch_bounds__(256) void add_ln_kernel(
    const float* __restrict__ xin, const float* __restrict__ res,
    const float* __restrict__ g, const float* __restrict__ bb,
    float* __restrict__ out)
{
    int t = blockIdx.x;
    int d = threadIdx.x;
    float v = xin[(size_t)t * Dz + d] + res[(size_t)t * Dz + d];
    float s = v, s2 = v * v;
    #pragma unroll
    for (int o = 16; o; o >>= 1) {
        s  += __shfl_xor_sync(0xffffffffu, s,  o);
        s2 += __shfl_xor_sync(0xffffffffu, s2, o);
    }
    __shared__ float ss[8], ss2[8];
    int w = d >> 5;
    if ((d & 31) == 0) { ss[w] = s; ss2[w] = s2; }
    __syncthreads();
    float ts = 0.f, ts2 = 0.f;
    #pragma unroll
    for (int i = 0; i < 8; i++) { ts += ss[i]; ts2 += ss2[i]; }
    float mean = ts * (1.f / 256.f);
    float var  = ts2 * (1.f / 256.f) - mean * mean;
    float rstd = rsqrtf(var + EPSz);
    out[(size_t)t * Dz + d] = (v - mean) * rstd * g[d] + bb[d];
}

// ---------------- launch ----------------
extern "C" void kernel_launch(void* const* d_in, const int* in_sizes, int n_in,
                              void* d_out, int out_size)
{
    (void)in_sizes; (void)n_in; (void)out_size;
    const int*   word   = (const int*)d_in[0];
    const int*   ngram  = (const int*)d_in[1];
    const float* fc1_w  = (const float*)d_in[2];
    const float* fc1_b  = (const float*)d_in[3];
    const float* fc2_w  = (const float*)d_in[4];
    const float* fc2_b  = (const float*)d_in[5];
    const float* qkv_w  = (const float*)d_in[6];
    const float* qkv_b  = (const float*)d_in[7];
    const float* out_w  = (const float*)d_in[8];
    const float* out_b  = (const float*)d_in[9];
    const float* ln1_g  = (const float*)d_in[10];
    const float* ln1_b  = (const float*)d_in[11];
    const float* ff1_w  = (const float*)d_in[12];
    const float* ff1_b  = (const float*)d_in[13];
    const float* ff2_w  = (const float*)d_in[14];
    const float* ff2_b  = (const float*)d_in[15];
    const float* ln2_g  = (const float*)d_in[16];
    const float* ln2_b  = (const float*)d_in[17];
    float* outp = (float*)d_out;

    float *h0, *x, *qkvb, *attno, *obuf, *f1, *f2;
    cudaGetSymbolAddress((void**)&h0,    g_h0);
    cudaGetSymbolAddress((void**)&x,     g_x);
    cudaGetSymbolAddress((void**)&qkvb,  g_qkv);
    cudaGetSymbolAddress((void**)&attno, g_attno);
    cudaGetSymbolAddress((void**)&obuf,  g_obuf);
    cudaGetSymbolAddress((void**)&f1,    g_f1);
    cudaGetSymbolAddress((void**)&f2,    g_f2);

    // 1. sparse embed -> relu(h0) [2048, 512]
    embed_kernel<<<Tz, 512>>>(word, ngram, fc1_w, fc1_b, h0);

    // 2. fc2: x = h0 @ fc2_w^T + b  [2048, 256]
    gemm_kernel<false><<<dim3(Dz / 64, Tz / 64), 256>>>(h0, fc2_w, fc2_b, x, Tz, Dz, FFDz);

    for (int i = 0; i < NLz; i++) {
        const float* qw = qkv_w + (size_t)i * 3 * Dz * Dz;
        const float* qb = qkv_b + (size_t)i * 3 * Dz;
        const float* ow = out_w + (size_t)i * Dz * Dz;
        const float* ob = out_b + (size_t)i * Dz;
        const float* f1w = ff1_w + (size_t)i * DFFz * Dz;
        const float* f1b = ff1_b + (size_t)i * DFFz;
        const float* f2w = ff2_w + (size_t)i * Dz * DFFz;
        const float* f2b = ff2_b + (size_t)i * Dz;

        // qkv projection [2048, 768]
        gemm_kernel<false><<<dim3(3 * Dz / 64, Tz / 64), 256>>>(x, qw, qb, qkvb, Tz, 3 * Dz, Dz);
        // attention [2048, 256]
        attn_kernel<<<Bz * Hz, 128>>>(qkvb, attno);
        // out projection
        gemm_kernel<false><<<dim3(Dz / 64, Tz / 64), 256>>>(attno, ow, ob, obuf, Tz, Dz, Dz);
        // x = LN(x + o)
        add_ln_kernel<<<Tz, 256>>>(x, obuf, ln1_g + i * Dz, ln1_b + i * Dz, x);
        // ff1 + relu [2048, 1024]
        gemm_kernel<true><<<dim3(DFFz / 64, Tz / 64), 256>>>(x, f1w, f1b, f1, Tz, DFFz, Dz);
        // ff2 [2048, 256]
        gemm_kernel<false><<<dim3(Dz / 64, Tz / 64), 256>>>(f1, f2w, f2b, f2, Tz, Dz, DFFz);
        // x = LN(x + f2); final layer writes straight to d_out
        float* dst = (i == NLz - 1) ? outp : x;
        add_ln_kernel<<<Tz, 256>>>(x, f2, ln2_g + i * Dz, ln2_b + i * Dz, dst);
    }
}

// round 5
// speedup vs baseline: 1.5853x; 1.5853x over previous
#include <cuda_runtime.h>
#include <cuda_bf16.h>
#include <cstdint>
#include <cstddef>

// ---------------- problem dims ----------------
#define WORDN 30000
#define FDIM  80000
#define Bz 32
#define Lz 64
#define Tz 2048
#define Kz 6
#define Dz 256
#define Hz 8
#define FFDz 512
#define DFFz 1024
#define NLz 2
#define EPSz 1e-5f

__device__ __forceinline__ uint32_t smem_u32(const void* p) {
    uint32_t a;
    asm("{ .reg .u64 t; cvta.to.shared.u64 t, %1; cvt.u32.u64 %0, t; }" : "=r"(a) : "l"(p));
    return a;
}

__device__ __forceinline__ void ldsm4(uint32_t* r, uint32_t addr) {
    asm volatile("ldmatrix.sync.aligned.m8n8.x4.shared.b16 {%0,%1,%2,%3}, [%4];"
        : "=r"(r[0]), "=r"(r[1]), "=r"(r[2]), "=r"(r[3]) : "r"(addr));
}

__device__ __forceinline__ void mma16816(float* d, const uint32_t* a, const uint32_t* b) {
    asm volatile("mma.sync.aligned.m16n8k16.row.col.f32.bf16.bf16.f32 "
        "{%0,%1,%2,%3}, {%4,%5,%6,%7}, {%8,%9}, {%0,%1,%2,%3};"
        : "+f"(d[0]), "+f"(d[1]), "+f"(d[2]), "+f"(d[3])
        : "r"(a[0]), "r"(a[1]), "r"(a[2]), "r"(a[3]), "r"(b[0]), "r"(b[1]));
}

// ================= scratch (no allocation allowed) =================
__device__ __align__(128) __nv_bfloat16 g_wfc2h[FFDz * Dz],         g_wfc2l[FFDz * Dz];
__device__ __align__(128) __nv_bfloat16 g_wqkvh[NLz * 3 * Dz * Dz], g_wqkvl[NLz * 3 * Dz * Dz];
__device__ __align__(128) __nv_bfloat16 g_wouth[NLz * Dz * Dz],     g_woutl[NLz * Dz * Dz];
__device__ __align__(128) __nv_bfloat16 g_wff1h[NLz * DFFz * Dz],   g_wff1l[NLz * DFFz * Dz];
__device__ __align__(128) __nv_bfloat16 g_wff2h[NLz * Dz * DFFz],   g_wff2l[NLz * Dz * DFFz];
__device__ __align__(128) __nv_bfloat16 g_h0h[Tz * FFDz],  g_h0l[Tz * FFDz];
__device__ __align__(128) __nv_bfloat16 g_xh[Tz * Dz],     g_xl[Tz * Dz];
__device__ __align__(128) __nv_bfloat16 g_aoh[Tz * Dz],    g_aol[Tz * Dz];
__device__ __align__(128) __nv_bfloat16 g_f1h[Tz * DFFz],  g_f1l[Tz * DFFz];
__device__ __align__(128) float g_x[Tz * Dz];
__device__ __align__(128) float g_qkv[Tz * 3 * Dz];
__device__ __align__(128) float g_obuf[Tz * Dz];
__device__ __align__(128) float g_f2[Tz * Dz];

// ================= weight fp32 -> bf16 hi/lo =================
__global__ __launch_bounds__(256) void convert_kernel(
    const float* __restrict__ in, __nv_bfloat16* __restrict__ hi,
    __nv_bfloat16* __restrict__ lo, int n)
{
    int i = blockIdx.x * 256 + threadIdx.x;
    if (i < n) {
        float v = in[i];
        __nv_bfloat16 h = __float2bfloat16(v);
        hi[i] = h;
        lo[i] = __float2bfloat16(v - __bfloat162float(h));
    }
}

// ================= embed: gather fc1_w cols, relu, write hi/lo =================
__global__ __launch_bounds__(512) void embed_kernel(
    const int* __restrict__ word, const int* __restrict__ ngram,
    const float* __restrict__ fc1w, const float* __restrict__ fc1b,
    __nv_bfloat16* __restrict__ h0h, __nv_bfloat16* __restrict__ h0l)
{
    int t = blockIdx.x;
    __shared__ int cols[7];
    __shared__ int ncols_s;
    if (threadIdx.x == 0) {
        int n = 0;
        cols[n++] = word[t];
        for (int k = 0; k < Kz; k++) {
            int c = WORDN + ngram[t * Kz + k];
            bool dup = false;
            for (int j = 1; j < n; j++) if (cols[j] == c) dup = true;
            if (!dup) cols[n++] = c;
        }
        ncols_s = n;
    }
    __syncthreads();
    int r = threadIdx.x;
    int n = ncols_s;
    const float* row = fc1w + (size_t)r * FDIM;
    float s = fc1b[r];
    for (int i = 0; i < n; i++) s += __ldg(row + cols[i]);
    s = fmaxf(s, 0.0f);
    __nv_bfloat16 h = __float2bfloat16(s);
    size_t o = (size_t)t * FFDz + r;
    h0h[o] = h;
    h0l[o] = __float2bfloat16(s - __bfloat162float(h));
}

// ================= split-bf16 GEMM via mma.sync m16n8k16 =================
// C[M,N] = (Ahi+Alo)[M,K] @ (Whi+Wlo)[N,K]^T + bias  (3-term, AloWlo dropped)
// BM = MI*64 (MI=1 or 2), BN=64, BK=32, 256 threads / 8 warps, warp tile (MI*16)x32.
// smem rows padded to 40 bf16 (80B) -> ldmatrix conflict-free (r*5 mod 8 distinct).
template<int MI, bool RELU, bool WF32, bool WBF16>
__global__ __launch_bounds__(256) void gemm_mma(
    const __nv_bfloat16* __restrict__ Ahi, const __nv_bfloat16* __restrict__ Alo,
    const __nv_bfloat16* __restrict__ Whi, const __nv_bfloat16* __restrict__ Wlo,
    const float* __restrict__ bias, float* __restrict__ C,
    __nv_bfloat16* __restrict__ Chi, __nv_bfloat16* __restrict__ Clo,
    int N, int K)
{
    constexpr int BM  = MI * 64;
    constexpr int LDA = 40;                 // bf16 per smem row (80 B)
    __shared__ __align__(16) __nv_bfloat16 sA[2][BM * LDA];
    __shared__ __align__(16) __nv_bfloat16 sB[2][64 * LDA];

    int tid = threadIdx.x, lane = tid & 31, wid = tid >> 5;
    int warp_m = wid & 3, warp_n = wid >> 2;
    int m0 = blockIdx.y * BM, n0 = blockIdx.x * 64;

    constexpr int NA = BM / 64;             // uint4 loads per thread per A buffer
    uint4 rA[2][NA], rB[2];

    uint32_t sAb = smem_u32(&sA[0][0]);
    uint32_t sBb = smem_u32(&sB[0][0]);
    constexpr uint32_t ABYTES = BM * LDA * 2;
    constexpr uint32_t BBYTES = 64 * LDA * 2;

    float acc[MI][4][4];
    #pragma unroll
    for (int mi = 0; mi < MI; mi++)
        #pragma unroll
        for (int ni = 0; ni < 4; ni++)
            #pragma unroll
            for (int j = 0; j < 4; j++) acc[mi][ni][j] = 0.f;

    int nk = K >> 5;

    // preload chunk 0
    {
        #pragma unroll
        for (int i = 0; i < NA; i++) {
            int idx = tid + i * 256;
            int row = idx >> 2, ch = idx & 3;
            size_t g = (size_t)(m0 + row) * K + ch * 8;
            rA[0][i] = *(const uint4*)(Ahi + g);
            rA[1][i] = *(const uint4*)(Alo + g);
        }
        int row = tid >> 2, ch = tid & 3;
        size_t g = (size_t)(n0 + row) * K + ch * 8;
        rB[0] = *(const uint4*)(Whi + g);
        rB[1] = *(const uint4*)(Wlo + g);
    }

    for (int kc = 0; kc < nk; kc++) {
        // store staged regs -> smem
        #pragma unroll
        for (int i = 0; i < NA; i++) {
            int idx = tid + i * 256;
            int row = idx >> 2, ch = idx & 3;
            *(uint4*)(&sA[0][row * LDA + ch * 8]) = rA[0][i];
            *(uint4*)(&sA[1][row * LDA + ch * 8]) = rA[1][i];
        }
        {
            int row = tid >> 2, ch = tid & 3;
            *(uint4*)(&sB[0][row * LDA + ch * 8]) = rB[0];
            *(uint4*)(&sB[1][row * LDA + ch * 8]) = rB[1];
        }
        __syncthreads();

        // prefetch next chunk
        if (kc + 1 < nk) {
            size_t kb = (size_t)(kc + 1) * 32;
            #pragma unroll
            for (int i = 0; i < NA; i++) {
                int idx = tid + i * 256;
                int row = idx >> 2, ch = idx & 3;
                size_t g = (size_t)(m0 + row) * K + kb + ch * 8;
                rA[0][i] = *(const uint4*)(Ahi + g);
                rA[1][i] = *(const uint4*)(Alo + g);
            }
            int row = tid >> 2, ch = tid & 3;
            size_t g = (size_t)(n0 + row) * K + kb + ch * 8;
            rB[0] = *(const uint4*)(Whi + g);
            rB[1] = *(const uint4*)(Wlo + g);
        }

        // compute: 2 k16 steps
        #pragma unroll
        for (int ks = 0; ks < 2; ks++) {
            uint32_t af[2][MI][4];
            #pragma unroll
            for (int mi = 0; mi < MI; mi++) {
                uint32_t row = warp_m * (MI * 16) + mi * 16 + (lane & 15);
                uint32_t cb  = ks * 32 + (lane >> 4) * 16;   // byte offset in row
                uint32_t off = row * 80 + cb;
                ldsm4(af[0][mi], sAb + off);
                ldsm4(af[1][mi], sAb + ABYTES + off);
            }
            uint32_t bf[2][2][4];
            #pragma unroll
            for (int n2 = 0; n2 < 2; n2++) {
                uint32_t nrow = warp_n * 32 + n2 * 16 + ((lane >> 4) & 1) * 8 + (lane & 7);
                uint32_t kb_  = ks * 32 + ((lane >> 3) & 1) * 16;
                uint32_t off = nrow * 80 + kb_;
                ldsm4(bf[0][n2], sBb + off);
                ldsm4(bf[1][n2], sBb + BBYTES + off);
            }
            #pragma unroll
            for (int mi = 0; mi < MI; mi++)
                #pragma unroll
                for (int ni = 0; ni < 4; ni++) {
                    int n2 = ni >> 1, s = (ni & 1) * 2;
                    uint32_t bh[2] = {bf[0][n2][s], bf[0][n2][s + 1]};
                    uint32_t bl[2] = {bf[1][n2][s], bf[1][n2][s + 1]};
                    mma16816(acc[mi][ni], af[0][mi], bh);   // Ahi*Whi
                    mma16816(acc[mi][ni], af[1][mi], bh);   // Alo*Whi
                    mma16816(acc[mi][ni], af[0][mi], bl);   // Ahi*Wlo
                }
        }
        __syncthreads();
    }

    // epilogue
    #pragma unroll
    for (int mi = 0; mi < MI; mi++)
        #pragma unroll
        for (int ni = 0; ni < 4; ni++) {
            int r = m0 + warp_m * (MI * 16) + mi * 16 + (lane >> 2);
            int c = n0 + warp_n * 32 + ni * 8 + (lane & 3) * 2;
            float b0 = bias[c], b1 = bias[c + 1];
            float v00 = acc[mi][ni][0] + b0, v01 = acc[mi][ni][1] + b1;
            float v10 = acc[mi][ni][2] + b0, v11 = acc[mi][ni][3] + b1;
            if (RELU) {
                v00 = fmaxf(v00, 0.f); v01 = fmaxf(v01, 0.f);
                v10 = fmaxf(v10, 0.f); v11 = fmaxf(v11, 0.f);
            }
            size_t o0 = (size_t)r * N + c;
            size_t o1 = (size_t)(r + 8) * N + c;
            if (WF32) {
                *(float2*)(C + o0) = make_float2(v00, v01);
                *(float2*)(C + o1) = make_float2(v10, v11);
            }
            if (WBF16) {
                __nv_bfloat16 h00 = __float2bfloat16(v00), h01 = __float2bfloat16(v01);
                __nv_bfloat16 h10 = __float2bfloat16(v10), h11 = __float2bfloat16(v11);
                *(__nv_bfloat162*)(Chi + o0) = __nv_bfloat162(h00, h01);
                *(__nv_bfloat162*)(Chi + o1) = __nv_bfloat162(h10, h11);
                *(__nv_bfloat162*)(Clo + o0) = __nv_bfloat162(
                    __float2bfloat16(v00 - __bfloat162float(h00)),
                    __float2bfloat16(v01 - __bfloat162float(h01)));
                *(__nv_bfloat162*)(Clo + o1) = __nv_bfloat162(
                    __float2bfloat16(v10 - __bfloat162float(h10)),
                    __float2bfloat16(v11 - __bfloat162float(h11)));
            }
        }
}

// ================= attention: one block per (b,h), 256 threads =================
__global__ __launch_bounds__(256) void attn_kernel(
    const float* __restrict__ qkv,
    __nv_bfloat16* __restrict__ oh, __nv_bfloat16* __restrict__ ol)
{
    int bh = blockIdx.x;
    int b = bh >> 3, h = bh & 7;
    __shared__ float Q[64][33], Ksm[64][33], V[64][33];
    __shared__ float S[64][65];
    int tid = threadIdx.x;
    const float scale = 0.17677669529663687f;  // 1/sqrt(32)

    for (int idx = tid; idx < 64 * 32; idx += 256) {
        int l = idx >> 5, j = idx & 31;
        size_t base = (size_t)(b * 64 + l) * (3 * Dz) + h * 32 + j;
        Q[l][j]   = qkv[base];
        Ksm[l][j] = qkv[base + Dz];
        V[l][j]   = qkv[base + 2 * Dz];
    }
    __syncthreads();

    for (int idx = tid; idx < 64 * 64; idx += 256) {
        int i = idx >> 6, j = idx & 63;
        float s = 0.f;
        #pragma unroll
        for (int d = 0; d < 32; d++) s += Q[i][d] * Ksm[j][d];
        S[i][j] = s * scale;
    }
    __syncthreads();

    if (tid < 64) {
        int i = tid;
        float m = -1e30f;
        #pragma unroll 8
        for (int j = 0; j < 64; j++) m = fmaxf(m, S[i][j]);
        float sum = 0.f;
        #pragma unroll 8
        for (int j = 0; j < 64; j++) { float e = __expf(S[i][j] - m); S[i][j] = e; sum += e; }
        float inv = 1.f / sum;
        #pragma unroll 8
        for (int j = 0; j < 64; j++) S[i][j] *= inv;
    }
    __syncthreads();

    for (int idx = tid; idx < 64 * 32; idx += 256) {
        int i = idx >> 5, d = idx & 31;
        float s = 0.f;
        #pragma unroll
        for (int j = 0; j < 64; j++) s += S[i][j] * V[j][d];
        size_t o = (size_t)(b * 64 + i) * Dz + h * 32 + d;
        __nv_bfloat16 hh = __float2bfloat16(s);
        oh[o] = hh;
        ol[o] = __float2bfloat16(s - __bfloat162float(hh));
    }
}

// ================= residual add + layernorm (+ optional hi/lo out) =================
__global__ __launch_bounds__(256) void add_ln_kernel(
    const float* __restrict__ xin, const float* __restrict__ res,
    const float* __restrict__ g, const float* __restrict__ bb,
    float* __restrict__ out,
    __nv_bfloat16* __restrict__ ohi, __nv_bfloat16* __restrict__ olo)
{
    int t = blockIdx.x;
    int d = threadIdx.x;
    float v = xin[(size_t)t * Dz + d] + res[(size_t)t * Dz + d];
    float s = v, s2 = v * v;
    #pragma unroll
    for (int o = 16; o; o >>= 1) {
        s  += __shfl_xor_sync(0xffffffffu, s,  o);
        s2 += __shfl_xor_sync(0xffffffffu, s2, o);
    }
    __shared__ float ss[8], ss2[8];
    int w = d >> 5;
    if ((d & 31) == 0) { ss[w] = s; ss2[w] = s2; }
    __syncthreads();
    float ts = 0.f, ts2 = 0.f;
    #pragma unroll
    for (int i = 0; i < 8; i++) { ts += ss[i]; ts2 += ss2[i]; }
    float mean = ts * (1.f / 256.f);
    float var  = ts2 * (1.f / 256.f) - mean * mean;
    float rstd = rsqrtf(var + EPSz);
    float r = (v - mean) * rstd * g[d] + bb[d];
    size_t o = (size_t)t * Dz + d;
    out[o] = r;
    if (ohi) {
        __nv_bfloat16 h = __float2bfloat16(r);
        ohi[o] = h;
        olo[o] = __float2bfloat16(r - __bfloat162float(h));
    }
}

// ================= launch =================
extern "C" void kernel_launch(void* const* d_in, const int* in_sizes, int n_in,
                              void* d_out, int out_size)
{
    (void)in_sizes; (void)n_in; (void)out_size;
    const int*   word   = (const int*)d_in[0];
    const int*   ngram  = (const int*)d_in[1];
    const float* fc1_w  = (const float*)d_in[2];
    const float* fc1_b  = (const float*)d_in[3];
    const float* fc2_w  = (const float*)d_in[4];
    const float* fc2_b  = (const float*)d_in[5];
    const float* qkv_w  = (const float*)d_in[6];
    const float* qkv_b  = (const float*)d_in[7];
    const float* out_w  = (const float*)d_in[8];
    const float* out_b  = (const float*)d_in[9];
    const float* ln1_g  = (const float*)d_in[10];
    const float* ln1_b  = (const float*)d_in[11];
    const float* ff1_w  = (const float*)d_in[12];
    const float* ff1_b  = (const float*)d_in[13];
    const float* ff2_w  = (const float*)d_in[14];
    const float* ff2_b  = (const float*)d_in[15];
    const float* ln2_g  = (const float*)d_in[16];
    const float* ln2_b  = (const float*)d_in[17];
    float* outp = (float*)d_out;

    __nv_bfloat16 *wfc2h, *wfc2l, *wqkvh, *wqkvl, *wouth, *woutl, *wff1h, *wff1l, *wff2h, *wff2l;
    __nv_bfloat16 *h0h, *h0l, *xh, *xl, *aoh, *aol, *f1h, *f1l;
    float *x, *qkvf, *obuf, *f2;
    cudaGetSymbolAddress((void**)&wfc2h, g_wfc2h); cudaGetSymbolAddress((void**)&wfc2l, g_wfc2l);
    cudaGetSymbolAddress((void**)&wqkvh, g_wqkvh); cudaGetSymbolAddress((void**)&wqkvl, g_wqkvl);
    cudaGetSymbolAddress((void**)&wouth, g_wouth); cudaGetSymbolAddress((void**)&woutl, g_woutl);
    cudaGetSymbolAddress((void**)&wff1h, g_wff1h); cudaGetSymbolAddress((void**)&wff1l, g_wff1l);
    cudaGetSymbolAddress((void**)&wff2h, g_wff2h); cudaGetSymbolAddress((void**)&wff2l, g_wff2l);
    cudaGetSymbolAddress((void**)&h0h, g_h0h);     cudaGetSymbolAddress((void**)&h0l, g_h0l);
    cudaGetSymbolAddress((void**)&xh, g_xh);       cudaGetSymbolAddress((void**)&xl, g_xl);
    cudaGetSymbolAddress((void**)&aoh, g_aoh);     cudaGetSymbolAddress((void**)&aol, g_aol);
    cudaGetSymbolAddress((void**)&f1h, g_f1h);     cudaGetSymbolAddress((void**)&f1l, g_f1l);
    cudaGetSymbolAddress((void**)&x, g_x);
    cudaGetSymbolAddress((void**)&qkvf, g_qkv);
    cudaGetSymbolAddress((void**)&obuf, g_obuf);
    cudaGetSymbolAddress((void**)&f2, g_f2);

    // weight hi/lo conversion
    {
        int n;
        n = FFDz * Dz;          convert_kernel<<<(n + 255) / 256, 256>>>(fc2_w, wfc2h, wfc2l, n);
        n = NLz * 3 * Dz * Dz;  convert_kernel<<<(n + 255) / 256, 256>>>(qkv_w, wqkvh, wqkvl, n);
        n = NLz * Dz * Dz;      convert_kernel<<<(n + 255) / 256, 256>>>(out_w, wouth, woutl, n);
        n = NLz * DFFz * Dz;    convert_kernel<<<(n + 255) / 256, 256>>>(ff1_w, wff1h, wff1l, n);
        n = NLz * Dz * DFFz;    convert_kernel<<<(n + 255) / 256, 256>>>(ff2_w, wff2h, wff2l, n);
    }

    // sparse embed -> relu -> h0 hi/lo  [2048, 512]
    embed_kernel<<<Tz, 512>>>(word, ngram, fc1_w, fc1_b, h0h, h0l);

    // fc2: x = h0 @ fc2_w^T + b  [2048, 256]  (fp32 + hi/lo out) — MI=1, grid 4x32
    gemm_mma<1, false, true, true><<<dim3(Dz / 64, Tz / 64), 256>>>(
        h0h, h0l, wfc2h, wfc2l, fc2_b, x, xh, xl, Dz, FFDz);

    for (int i = 0; i < NLz; i++) {
        const __nv_bfloat16* qwh = wqkvh + (size_t)i * 3 * Dz * Dz;
        const __nv_bfloat16* qwl = wqkvl + (size_t)i * 3 * Dz * Dz;
        const __nv_bfloat16* owh = wouth + (size_t)i * Dz * Dz;
        const __nv_bfloat16* owl = woutl + (size_t)i * Dz * Dz;
        const __nv_bfloat16* f1wh = wff1h + (size_t)i * DFFz * Dz;
        const __nv_bfloat16* f1wl = wff1l + (size_t)i * DFFz * Dz;
        const __nv_bfloat16* f2wh = wff2h + (size_t)i * Dz * DFFz;
        const __nv_bfloat16* f2wl = wff2l + (size_t)i * Dz * DFFz;

        // qkv projection [2048, 768] — MI=2, grid 12x16
        gemm_mma<2, false, true, false><<<dim3(3 * Dz / 64, Tz / 128), 256>>>(
            xh, xl, qwh, qwl, qkv_b + (size_t)i * 3 * Dz, qkvf, nullptr, nullptr, 3 * Dz, Dz);
        // attention -> attno hi/lo
        attn_kernel<<<Bz * Hz, 256>>>(qkvf, aoh, aol);
        // out projection [2048, 256] — MI=1, grid 4x32
        gemm_mma<1, false, true, false><<<dim3(Dz / 64, Tz / 64), 256>>>(
            aoh, aol, owh, owl, out_b + (size_t)i * Dz, obuf, nullptr, nullptr, Dz, Dz);
        // x = LN(x + o), fp32 + hi/lo
        add_ln_kernel<<<Tz, 256>>>(x, obuf, ln1_g + i * Dz, ln1_b + i * Dz, x, xh, xl);
        // ff1 + relu [2048, 1024] hi/lo only — MI=2, grid 16x16
        gemm_mma<2, true, false, true><<<dim3(DFFz / 64, Tz / 128), 256>>>(
            xh, xl, f1wh, f1wl, ff1_b + (size_t)i * DFFz, nullptr, f1h, f1l, DFFz, Dz);
        // ff2 [2048, 256] — MI=1, grid 4x32, K=1024
        gemm_mma<1, false, true, false><<<dim3(Dz / 64, Tz / 64), 256>>>(
            f1h, f1l, f2wh, f2wl, ff2_b + (size_t)i * Dz, f2, nullptr, nullptr, Dz, DFFz);
        // x = LN(x + f2); final layer -> d_out (fp32 only)
        bool last = (i == NLz - 1);
        add_ln_kernel<<<Tz, 256>>>(x, f2, ln2_g + i * Dz, ln2_b + i * Dz,
                                   last ? outp : x,
                                   last ? nullptr : xh, last ? nullptr : xl);
    }
}

// round 7
// speedup vs baseline: 1.7632x; 1.1123x over previous
#include <cuda_runtime.h>
#include <cuda_bf16.h>
#include <cstdint>
#include <cstddef>

// ---------------- problem dims ----------------
#define WORDN 30000
#define FDIM  80000
#define Bz 32
#define Lz 64
#define Tz 2048
#define Kz 6
#define Dz 256
#define Hz 8
#define FFDz 512
#define DFFz 1024
#define NLz 2
#define EPSz 1e-5f

__device__ __forceinline__ uint32_t smem_u32(const void* p) {
    uint32_t a;
    asm("{ .reg .u64 t; cvta.to.shared.u64 t, %1; cvt.u32.u64 %0, t; }" : "=r"(a) : "l"(p));
    return a;
}

__device__ __forceinline__ void ldsm4(uint32_t* r, uint32_t addr) {
    asm volatile("ldmatrix.sync.aligned.m8n8.x4.shared.b16 {%0,%1,%2,%3}, [%4];"
        : "=r"(r[0]), "=r"(r[1]), "=r"(r[2]), "=r"(r[3]) : "r"(addr));
}

__device__ __forceinline__ void mma16816(float* d, const uint32_t* a, const uint32_t* b) {
    asm volatile("mma.sync.aligned.m16n8k16.row.col.f32.bf16.bf16.f32 "
        "{%0,%1,%2,%3}, {%4,%5,%6,%7}, {%8,%9}, {%0,%1,%2,%3};"
        : "+f"(d[0]), "+f"(d[1]), "+f"(d[2]), "+f"(d[3])
        : "r"(a[0]), "r"(a[1]), "r"(a[2]), "r"(a[3]), "r"(b[0]), "r"(b[1]));
}

__device__ __forceinline__ void cp_async16(uint32_t saddr, const void* gptr) {
    asm volatile("cp.async.cg.shared.global [%0], [%1], 16;" :: "r"(saddr), "l"(gptr));
}
#define CP_COMMIT() asm volatile("cp.async.commit_group;" ::: "memory")
#define CP_WAIT0()  asm volatile("cp.async.wait_group 0;" ::: "memory")

// ================= scratch (no allocation allowed) =================
__device__ __align__(128) __nv_bfloat16 g_wfc2h[FFDz * Dz],         g_wfc2l[FFDz * Dz];
__device__ __align__(128) __nv_bfloat16 g_wqkvh[NLz * 3 * Dz * Dz], g_wqkvl[NLz * 3 * Dz * Dz];
__device__ __align__(128) __nv_bfloat16 g_wouth[NLz * Dz * Dz],     g_woutl[NLz * Dz * Dz];
__device__ __align__(128) __nv_bfloat16 g_wff1h[NLz * DFFz * Dz],   g_wff1l[NLz * DFFz * Dz];
__device__ __align__(128) __nv_bfloat16 g_wff2h[NLz * Dz * DFFz],   g_wff2l[NLz * Dz * DFFz];
__device__ __align__(128) __nv_bfloat16 g_h0h[Tz * FFDz],  g_h0l[Tz * FFDz];
__device__ __align__(128) __nv_bfloat16 g_xh[Tz * Dz],     g_xl[Tz * Dz];
__device__ __align__(128) __nv_bfloat16 g_aoh[Tz * Dz],    g_aol[Tz * Dz];
__device__ __align__(128) __nv_bfloat16 g_f1h[Tz * DFFz],  g_f1l[Tz * DFFz];
__device__ __align__(128) float g_x[Tz * Dz];
__device__ __align__(128) float g_qkv[Tz * 3 * Dz];
__device__ __align__(128) float g_obuf[Tz * Dz];
__device__ __align__(128) float g_f2[Tz * Dz];

// ================= fused weight fp32 -> bf16 hi/lo (all 5 weights) =================
// segment bounds (elements): fc2 131072 | qkv 393216 | out 131072 | ff1 524288 | ff2 524288
#define CE0 131072
#define CE1 524288
#define CE2 655360
#define CE3 1179648
#define CE4 1703936

__global__ __launch_bounds__(256) void convert_all_kernel(
    const float* __restrict__ fc2, const float* __restrict__ qkvw,
    const float* __restrict__ outw, const float* __restrict__ ff1,
    const float* __restrict__ ff2,
    __nv_bfloat16* __restrict__ fc2h, __nv_bfloat16* __restrict__ fc2l,
    __nv_bfloat16* __restrict__ qh,   __nv_bfloat16* __restrict__ ql,
    __nv_bfloat16* __restrict__ ohw,  __nv_bfloat16* __restrict__ olw,
    __nv_bfloat16* __restrict__ f1h,  __nv_bfloat16* __restrict__ f1l,
    __nv_bfloat16* __restrict__ f2h,  __nv_bfloat16* __restrict__ f2l)
{
    int q = blockIdx.x * 256 + threadIdx.x;
    long i = (long)q * 4;
    if (i >= CE4) return;
    const float* s; __nv_bfloat16 *hp, *lp; long off;
    if (i < CE0)      { s = fc2;  hp = fc2h; lp = fc2l; off = i; }
    else if (i < CE1) { s = qkvw; hp = qh;   lp = ql;   off = i - CE0; }
    else if (i < CE2) { s = outw; hp = ohw;  lp = olw;  off = i - CE1; }
    else if (i < CE3) { s = ff1;  hp = f1h;  lp = f1l;  off = i - CE2; }
    else              { s = ff2;  hp = f2h;  lp = f2l;  off = i - CE3; }
    float4 v = *(const float4*)(s + off);
    __nv_bfloat16 h0 = __float2bfloat16(v.x), h1 = __float2bfloat16(v.y);
    __nv_bfloat16 h2 = __float2bfloat16(v.z), h3 = __float2bfloat16(v.w);
    *(__nv_bfloat162*)(hp + off)     = __nv_bfloat162(h0, h1);
    *(__nv_bfloat162*)(hp + off + 2) = __nv_bfloat162(h2, h3);
    *(__nv_bfloat162*)(lp + off)     = __nv_bfloat162(
        __float2bfloat16(v.x - __bfloat162float(h0)),
        __float2bfloat16(v.y - __bfloat162float(h1)));
    *(__nv_bfloat162*)(lp + off + 2) = __nv_bfloat162(
        __float2bfloat16(v.z - __bfloat162float(h2)),
        __float2bfloat16(v.w - __bfloat162float(h3)));
}

// ================= embed: fixed-7 masked gather, relu, hi/lo =================
__global__ __launch_bounds__(512) void embed_kernel(
    const int* __restrict__ word, const int* __restrict__ ngram,
    const float* __restrict__ fc1w, const float* __restrict__ fc1b,
    __nv_bfloat16* __restrict__ h0h, __nv_bfloat16* __restrict__ h0l)
{
    int t = blockIdx.x;
    __shared__ int cols7[7];
    __shared__ float msk[7];
    if (threadIdx.x == 0) {
        cols7[0] = word[t];
        msk[0] = 1.f;
        #pragma unroll
        for (int k = 0; k < Kz; k++) {
            int c = WORDN + ngram[t * Kz + k];
            bool dup = false;
            for (int j = 1; j <= k; j++) if (cols7[j] == c) dup = true;
            cols7[k + 1] = c;
            msk[k + 1] = dup ? 0.f : 1.f;
        }
    }
    __syncthreads();
    int r = threadIdx.x;
    const float* row = fc1w + (size_t)r * FDIM;
    float s = fc1b[r];
    #pragma unroll
    for (int i = 0; i < 7; i++) s += msk[i] * __ldg(row + cols7[i]);
    s = fmaxf(s, 0.0f);
    __nv_bfloat16 h = __float2bfloat16(s);
    size_t o = (size_t)t * FFDz + r;
    h0h[o] = h;
    h0l[o] = __float2bfloat16(s - __bfloat162float(h));
}

// ================= split-bf16 GEMM via mma.sync m16n8k16 (cp.async pipelined) ====
// C[M,N] = (Ahi+Alo)[M,K] @ (Whi+Wlo)[N,K]^T + bias  (3-term, AloWlo dropped)
// BM = MI*64, BN=64, BK=32, 256 threads / 8 warps, warp tile (MI*16)x32.
// Double-buffered smem, 1 sync per K chunk. Rows 80B -> conflict-free ldmatrix.
template<int MI, bool RELU, bool WF32, bool WBF16>
__global__ __launch_bounds__(256) void gemm_mma(
    const __nv_bfloat16* __restrict__ Ahi, const __nv_bfloat16* __restrict__ Alo,
    const __nv_bfloat16* __restrict__ Whi, const __nv_bfloat16* __restrict__ Wlo,
    const float* __restrict__ bias, float* __restrict__ C,
    __nv_bfloat16* __restrict__ Chi, __nv_bfloat16* __restrict__ Clo,
    int N, int K)
{
    extern __shared__ __align__(16) char dsm[];
    constexpr int BM = MI * 64;
    constexpr uint32_t ABY  = BM * 80u;       // one A tile (hi or lo)
    constexpr uint32_t AALL = 2 * ABY;        // hi+lo, one buffer
    constexpr uint32_t BOFF = 2 * AALL;       // B region base
    constexpr uint32_t BBY  = 64 * 80u;
    constexpr uint32_t BALL = 2 * BBY;
    constexpr int NA = BM / 64;

    uint32_t sb = smem_u32(dsm);
    int tid = threadIdx.x, lane = tid & 31, wid = tid >> 5;
    int warp_m = wid & 3, warp_n = wid >> 2;
    int m0 = blockIdx.y * BM, n0 = blockIdx.x * 64;

    float acc[MI][4][4];
    #pragma unroll
    for (int mi = 0; mi < MI; mi++)
        #pragma unroll
        for (int ni = 0; ni < 4; ni++)
            #pragma unroll
            for (int j = 0; j < 4; j++) acc[mi][ni][j] = 0.f;

    int nk = K >> 5;

    auto load_chunk = [&](int kc, int bb) {
        size_t kb = (size_t)kc * 32;
        #pragma unroll
        for (int i2 = 0; i2 < NA; i2++) {
            int idx = tid + i2 * 256;
            int row = idx >> 2, ch = idx & 3;
            size_t g = (size_t)(m0 + row) * K + kb + ch * 8;
            uint32_t sa = sb + (uint32_t)bb * AALL + row * 80 + ch * 16;
            cp_async16(sa,       Ahi + g);
            cp_async16(sa + ABY, Alo + g);
        }
        {
            int row = tid >> 2, ch = tid & 3;
            size_t g = (size_t)(n0 + row) * K + kb + ch * 8;
            uint32_t sa = sb + BOFF + (uint32_t)bb * BALL + row * 80 + ch * 16;
            cp_async16(sa,       Whi + g);
            cp_async16(sa + BBY, Wlo + g);
        }
    };

    load_chunk(0, 0);
    CP_COMMIT();
    CP_WAIT0();
    __syncthreads();

    int bb = 0;
    for (int kc = 0; kc < nk; kc++) {
        if (kc + 1 < nk) { load_chunk(kc + 1, bb ^ 1); CP_COMMIT(); }

        uint32_t aB = sb + (uint32_t)bb * AALL;
        uint32_t bB = sb + BOFF + (uint32_t)bb * BALL;
        #pragma unroll
        for (int ks = 0; ks < 2; ks++) {
            uint32_t af[2][MI][4];
            #pragma unroll
            for (int mi = 0; mi < MI; mi++) {
                uint32_t row = warp_m * (MI * 16) + mi * 16 + (lane & 15);
                uint32_t cb  = ks * 32 + (lane >> 4) * 16;
                uint32_t off = row * 80 + cb;
                ldsm4(af[0][mi], aB + off);
                ldsm4(af[1][mi], aB + ABY + off);
            }
            uint32_t bf[2][2][4];
            #pragma unroll
            for (int n2 = 0; n2 < 2; n2++) {
                uint32_t nrow = warp_n * 32 + n2 * 16 + ((lane >> 4) & 1) * 8 + (lane & 7);
                uint32_t kb_  = ks * 32 + ((lane >> 3) & 1) * 16;
                uint32_t off  = nrow * 80 + kb_;
                ldsm4(bf[0][n2], bB + off);
                ldsm4(bf[1][n2], bB + BBY + off);
            }
            #pragma unroll
            for (int mi = 0; mi < MI; mi++)
                #pragma unroll
                for (int ni = 0; ni < 4; ni++) {
                    int n2 = ni >> 1, s = (ni & 1) * 2;
                    uint32_t bh[2] = {bf[0][n2][s], bf[0][n2][s + 1]};
                    uint32_t bl[2] = {bf[1][n2][s], bf[1][n2][s + 1]};
                    mma16816(acc[mi][ni], af[0][mi], bh);   // Ahi*Whi
                    mma16816(acc[mi][ni], af[1][mi], bh);   // Alo*Whi
                    mma16816(acc[mi][ni], af[0][mi], bl);   // Ahi*Wlo
                }
        }
        if (kc + 1 < nk) {
            CP_WAIT0();
            __syncthreads();
            bb ^= 1;
        }
    }

    // epilogue
    #pragma unroll
    for (int mi = 0; mi < MI; mi++)
        #pragma unroll
        for (int ni = 0; ni < 4; ni++) {
            int r = m0 + warp_m * (MI * 16) + mi * 16 + (lane >> 2);
            int c = n0 + warp_n * 32 + ni * 8 + (lane & 3) * 2;
            float b0 = bias[c], b1 = bias[c + 1];
            float v00 = acc[mi][ni][0] + b0, v01 = acc[mi][ni][1] + b1;
            float v10 = acc[mi][ni][2] + b0, v11 = acc[mi][ni][3] + b1;
            if (RELU) {
                v00 = fmaxf(v00, 0.f); v01 = fmaxf(v01, 0.f);
                v10 = fmaxf(v10, 0.f); v11 = fmaxf(v11, 0.f);
            }
            size_t o0 = (size_t)r * N + c;
            size_t o1 = (size_t)(r + 8) * N + c;
            if (WF32) {
                *(float2*)(C + o0) = make_float2(v00, v01);
                *(float2*)(C + o1) = make_float2(v10, v11);
            }
            if (WBF16) {
                __nv_bfloat16 h00 = __float2bfloat16(v00), h01 = __float2bfloat16(v01);
                __nv_bfloat16 h10 = __float2bfloat16(v10), h11 = __float2bfloat16(v11);
                *(__nv_bfloat162*)(Chi + o0) = __nv_bfloat162(h00, h01);
                *(__nv_bfloat162*)(Chi + o1) = __nv_bfloat162(h10, h11);
                *(__nv_bfloat162*)(Clo + o0) = __nv_bfloat162(
                    __float2bfloat16(v00 - __bfloat162float(h00)),
                    __float2bfloat16(v01 - __bfloat162float(h01)));
                *(__nv_bfloat162*)(Clo + o1) = __nv_bfloat162(
                    __float2bfloat16(v10 - __bfloat162float(h10)),
                    __float2bfloat16(v11 - __bfloat162float(h11)));
            }
        }
}

// ================= attention: one block per (b,h), 256 threads =================
// Q row in regs, float4 K/V reads, register softmax with 4-lane shfl.
__global__ __launch_bounds__(256) void attn_kernel(
    const float* __restrict__ qkv,
    __nv_bfloat16* __restrict__ oh, __nv_bfloat16* __restrict__ ol)
{
    int bh = blockIdx.x;
    int b = bh >> 3, h = bh & 7;
    __shared__ float Q[64][36], Ksm[64][36], V[64][36];
    __shared__ float S[64][68];
    int tid = threadIdx.x;
    const float scale = 0.17677669529663687f;  // 1/sqrt(32)

    for (int idx = tid; idx < 64 * 32; idx += 256) {
        int l = idx >> 5, j = idx & 31;
        size_t base = (size_t)(b * 64 + l) * (3 * Dz) + h * 32 + j;
        Q[l][j]   = qkv[base];
        Ksm[l][j] = qkv[base + Dz];
        V[l][j]   = qkv[base + 2 * Dz];
    }
    __syncthreads();

    int i = tid >> 2, g = tid & 3;      // row, lane-group
    float4 qr[8];
    #pragma unroll
    for (int u = 0; u < 8; u++) qr[u] = *(float4*)&Q[i][u * 4];

    float sv[16];
    #pragma unroll
    for (int t = 0; t < 16; t++) {
        int j = g + t * 4;
        float s = 0.f;
        #pragma unroll
        for (int u = 0; u < 8; u++) {
            float4 kv = *(float4*)&Ksm[j][u * 4];
            s += qr[u].x * kv.x + qr[u].y * kv.y + qr[u].z * kv.z + qr[u].w * kv.w;
        }
        sv[t] = s * scale;
    }
    // softmax across the 4 lanes of this row
    float m = -1e30f;
    #pragma unroll
    for (int t = 0; t < 16; t++) m = fmaxf(m, sv[t]);
    m = fmaxf(m, __shfl_xor_sync(0xffffffffu, m, 1));
    m = fmaxf(m, __shfl_xor_sync(0xffffffffu, m, 2));
    float sum = 0.f;
    #pragma unroll
    for (int t = 0; t < 16; t++) { sv[t] = __expf(sv[t] - m); sum += sv[t]; }
    sum += __shfl_xor_sync(0xffffffffu, sum, 1);
    sum += __shfl_xor_sync(0xffffffffu, sum, 2);
    float inv = 1.f / sum;
    #pragma unroll
    for (int t = 0; t < 16; t++) S[i][g + t * 4] = sv[t] * inv;
    __syncthreads();

    // AV: thread handles (row i2, 8 consecutive d)
    int i2 = tid >> 2, d0 = (tid & 3) * 8;
    float o[8];
    #pragma unroll
    for (int u = 0; u < 8; u++) o[u] = 0.f;
    #pragma unroll 4
    for (int j = 0; j < 64; j++) {
        float s = S[i2][j];
        float4 v0 = *(float4*)&V[j][d0];
        float4 v1 = *(float4*)&V[j][d0 + 4];
        o[0] += s * v0.x; o[1] += s * v0.y; o[2] += s * v0.z; o[3] += s * v0.w;
        o[4] += s * v1.x; o[5] += s * v1.y; o[6] += s * v1.z; o[7] += s * v1.w;
    }
    size_t ob = (size_t)(b * 64 + i2) * Dz + h * 32 + d0;
    #pragma unroll
    for (int u = 0; u < 4; u++) {
        __nv_bfloat16 ha = __float2bfloat16(o[u * 2]);
        __nv_bfloat16 hb = __float2bfloat16(o[u * 2 + 1]);
        *(__nv_bfloat162*)(oh + ob + u * 2) = __nv_bfloat162(ha, hb);
        *(__nv_bfloat162*)(ol + ob + u * 2) = __nv_bfloat162(
            __float2bfloat16(o[u * 2]     - __bfloat162float(ha)),
            __float2bfloat16(o[u * 2 + 1] - __bfloat162float(hb)));
    }
}

// ================= residual add + layernorm (+ optional hi/lo out) =================
__global__ __launch_bounds__(256) void add_ln_kernel(
    const float* __restrict__ xin, const float* __restrict__ res,
    const float* __restrict__ g, const float* __restrict__ bb,
    float* __restrict__ out,
    __nv_bfloat16* __restrict__ ohi, __nv_bfloat16* __restrict__ olo)
{
    int t = blockIdx.x;
    int d = threadIdx.x;
    float v = xin[(size_t)t * Dz + d] + res[(size_t)t * Dz + d];
    float s = v, s2 = v * v;
    #pragma unroll
    for (int o = 16; o; o >>= 1) {
        s  += __shfl_xor_sync(0xffffffffu, s,  o);
        s2 += __shfl_xor_sync(0xffffffffu, s2, o);
    }
    __shared__ float ss[8], ss2[8];
    int w = d >> 5;
    if ((d & 31) == 0) { ss[w] = s; ss2[w] = s2; }
    __syncthreads();
    float ts = 0.f, ts2 = 0.f;
    #pragma unroll
    for (int i = 0; i < 8; i++) { ts += ss[i]; ts2 += ss2[i]; }
    float mean = ts * (1.f / 256.f);
    float var  = ts2 * (1.f / 256.f) - mean * mean;
    float rstd = rsqrtf(var + EPSz);
    float r = (v - mean) * rstd * g[d] + bb[d];
    size_t o = (size_t)t * Dz + d;
    out[o] = r;
    if (ohi) {
        __nv_bfloat16 h = __float2bfloat16(r);
        ohi[o] = h;
        olo[o] = __float2bfloat16(r - __bfloat162float(h));
    }
}

// ================= launch =================
extern "C" void kernel_launch(void* const* d_in, const int* in_sizes, int n_in,
                              void* d_out, int out_size)
{
    (void)in_sizes; (void)n_in; (void)out_size;
    const int*   word   = (const int*)d_in[0];
    const int*   ngram  = (const int*)d_in[1];
    const float* fc1_w  = (const float*)d_in[2];
    const float* fc1_b  = (const float*)d_in[3];
    const float* fc2_w  = (const float*)d_in[4];
    const float* fc2_b  = (const float*)d_in[5];
    const float* qkv_w  = (const float*)d_in[6];
    const float* qkv_b  = (const float*)d_in[7];
    const float* out_w  = (const float*)d_in[8];
    const float* out_b  = (const float*)d_in[9];
    const float* ln1_g  = (const float*)d_in[10];
    const float* ln1_b  = (const float*)d_in[11];
    const float* ff1_w  = (const float*)d_in[12];
    const float* ff1_b  = (const float*)d_in[13];
    const float* ff2_w  = (const float*)d_in[14];
    const float* ff2_b  = (const float*)d_in[15];
    const float* ln2_g  = (const float*)d_in[16];
    const float* ln2_b  = (const float*)d_in[17];
    float* outp = (float*)d_out;

    __nv_bfloat16 *wfc2h, *wfc2l, *wqkvh, *wqkvl, *wouth, *woutl, *wff1h, *wff1l, *wff2h, *wff2l;
    __nv_bfloat16 *h0h, *h0l, *xh, *xl, *aoh, *aol, *f1h, *f1l;
    float *x, *qkvf, *obuf, *f2;
    cudaGetSymbolAddress((void**)&wfc2h, g_wfc2h); cudaGetSymbolAddress((void**)&wfc2l, g_wfc2l);
    cudaGetSymbolAddress((void**)&wqkvh, g_wqkvh); cudaGetSymbolAddress((void**)&wqkvl, g_wqkvl);
    cudaGetSymbolAddress((void**)&wouth, g_wouth); cudaGetSymbolAddress((void**)&woutl, g_woutl);
    cudaGetSymbolAddress((void**)&wff1h, g_wff1h); cudaGetSymbolAddress((void**)&wff1l, g_wff1l);
    cudaGetSymbolAddress((void**)&wff2h, g_wff2h); cudaGetSymbolAddress((void**)&wff2l, g_wff2l);
    cudaGetSymbolAddress((void**)&h0h, g_h0h);     cudaGetSymbolAddress((void**)&h0l, g_h0l);
    cudaGetSymbolAddress((void**)&xh, g_xh);       cudaGetSymbolAddress((void**)&xl, g_xl);
    cudaGetSymbolAddress((void**)&aoh, g_aoh);     cudaGetSymbolAddress((void**)&aol, g_aol);
    cudaGetSymbolAddress((void**)&f1h, g_f1h);     cudaGetSymbolAddress((void**)&f1l, g_f1l);
    cudaGetSymbolAddress((void**)&x, g_x);
    cudaGetSymbolAddress((void**)&qkvf, g_qkv);
    cudaGetSymbolAddress((void**)&obuf, g_obuf);
    cudaGetSymbolAddress((void**)&f2, g_f2);

    // dynamic smem limits (MI=2 needs >48KB)
    constexpr int SMEM1 = 40960, SMEM2 = 61440;
    cudaFuncSetAttribute(gemm_mma<1, false, true,  true >, cudaFuncAttributeMaxDynamicSharedMemorySize, SMEM1);
    cudaFuncSetAttribute(gemm_mma<1, false, true,  false>, cudaFuncAttributeMaxDynamicSharedMemorySize, SMEM1);
    cudaFuncSetAttribute(gemm_mma<2, false, true,  false>, cudaFuncAttributeMaxDynamicSharedMemorySize, SMEM2);
    cudaFuncSetAttribute(gemm_mma<2, true,  false, true >, cudaFuncAttributeMaxDynamicSharedMemorySize, SMEM2);

    // fused weight hi/lo conversion (1 launch)
    convert_all_kernel<<<CE4 / 4 / 256, 256>>>(
        fc2_w, qkv_w, out_w, ff1_w, ff2_w,
        wfc2h, wfc2l, wqkvh, wqkvl, wouth, woutl, wff1h, wff1l, wff2h, wff2l);

    // sparse embed -> relu -> h0 hi/lo  [2048, 512]
    embed_kernel<<<Tz, 512>>>(word, ngram, fc1_w, fc1_b, h0h, h0l);

    // fc2: x = h0 @ fc2_w^T + b  [2048, 256]  (fp32 + hi/lo out) — MI=1, grid 4x32
    gemm_mma<1, false, true, true><<<dim3(Dz / 64, Tz / 64), 256, SMEM1>>>(
        h0h, h0l, wfc2h, wfc2l, fc2_b, x, xh, xl, Dz, FFDz);

    for (int i = 0; i < NLz; i++) {
        const __nv_bfloat16* qwh = wqkvh + (size_t)i * 3 * Dz * Dz;
        const __nv_bfloat16* qwl = wqkvl + (size_t)i * 3 * Dz * Dz;
        const __nv_bfloat16* owh = wouth + (size_t)i * Dz * Dz;
        const __nv_bfloat16* owl = woutl + (size_t)i * Dz * Dz;
        const __nv_bfloat16* f1wh = wff1h + (size_t)i * DFFz * Dz;
        const __nv_bfloat16* f1wl = wff1l + (size_t)i * DFFz * Dz;
        const __nv_bfloat16* f2wh = wff2h + (size_t)i * Dz * DFFz;
        const __nv_bfloat16* f2wl = wff2l + (size_t)i * Dz * DFFz;

        // qkv projection [2048, 768] — MI=2, grid 12x16
        gemm_mma<2, false, true, false><<<dim3(3 * Dz / 64, Tz / 128), 256, SMEM2>>>(
            xh, xl, qwh, qwl, qkv_b + (size_t)i * 3 * Dz, qkvf, nullptr, nullptr, 3 * Dz, Dz);
        // attention -> attno hi/lo
        attn_kernel<<<Bz * Hz, 256>>>(qkvf, aoh, aol);
        // out projection [2048, 256] — MI=1, grid 4x32
        gemm_mma<1, false, true, false><<<dim3(Dz / 64, Tz / 64), 256, SMEM1>>>(
            aoh, aol, owh, owl, out_b + (size_t)i * Dz, obuf, nullptr, nullptr, Dz, Dz);
        // x = LN(x + o), fp32 + hi/lo
        add_ln_kernel<<<Tz, 256>>>(x, obuf, ln1_g + i * Dz, ln1_b + i * Dz, x, xh, xl);
        // ff1 + relu [2048, 1024] hi/lo only — MI=2, grid 16x16
        gemm_mma<2, true, false, true><<<dim3(DFFz / 64, Tz / 128), 256, SMEM2>>>(
            xh, xl, f1wh, f1wl, ff1_b + (size_t)i * DFFz, nullptr, f1h, f1l, DFFz, Dz);
        // ff2 [2048, 256] — MI=1, grid 4x32, K=1024
        gemm_mma<1, false, true, false><<<dim3(Dz / 64, Tz / 64), 256, SMEM1>>>(
            f1h, f1l, f2wh, f2wl, ff2_b + (size_t)i * Dz, f2, nullptr, nullptr, Dz, DFFz);
        // x = LN(x + f2); final layer -> d_out (fp32 only)
        bool last = (i == NLz - 1);
        add_ln_kernel<<<Tz, 256>>>(x, f2, ln2_g + i * Dz, ln2_b + i * Dz,
                                   last ? outp : x,
                                   last ? nullptr : xh, last ? nullptr : xl);
    }
}

// round 9
// speedup vs baseline: 1.9045x; 1.0801x over previous
#include <cuda_runtime.h>
#include <cuda_bf16.h>
#include <cstdint>
#include <cstddef>

// ---------------- problem dims ----------------
#define WORDN 30000
#define FDIM  80000
#define Bz 32
#define Lz 64
#define Tz 2048
#define Kz 6
#define Dz 256
#define Hz 8
#define FFDz 512
#define DFFz 1024
#define NLz 2
#define EPSz 1e-5f

__device__ __forceinline__ uint32_t smem_u32(const void* p) {
    uint32_t a;
    asm("{ .reg .u64 t; cvta.to.shared.u64 t, %1; cvt.u32.u64 %0, t; }" : "=r"(a) : "l"(p));
    return a;
}

__device__ __forceinline__ void ldsm4(uint32_t* r, uint32_t addr) {
    asm volatile("ldmatrix.sync.aligned.m8n8.x4.shared.b16 {%0,%1,%2,%3}, [%4];"
        : "=r"(r[0]), "=r"(r[1]), "=r"(r[2]), "=r"(r[3]) : "r"(addr));
}

__device__ __forceinline__ void mma16816(float* d, const uint32_t* a, const uint32_t* b) {
    asm volatile("mma.sync.aligned.m16n8k16.row.col.f32.bf16.bf16.f32 "
        "{%0,%1,%2,%3}, {%4,%5,%6,%7}, {%8,%9}, {%0,%1,%2,%3};"
        : "+f"(d[0]), "+f"(d[1]), "+f"(d[2]), "+f"(d[3])
        : "r"(a[0]), "r"(a[1]), "r"(a[2]), "r"(a[3]), "r"(b[0]), "r"(b[1]));
}

__device__ __forceinline__ void cp_async16(uint32_t saddr, const void* gptr) {
    asm volatile("cp.async.cg.shared.global [%0], [%1], 16;" :: "r"(saddr), "l"(gptr));
}
#define CP_COMMIT() asm volatile("cp.async.commit_group;" ::: "memory")
#define CP_WAIT0()  asm volatile("cp.async.wait_group 0;" ::: "memory")

// ================= scratch (no allocation allowed) =================
__device__ __align__(128) __nv_bfloat16 g_wfc2h[FFDz * Dz],         g_wfc2l[FFDz * Dz];
__device__ __align__(128) __nv_bfloat16 g_wqkvh[NLz * 3 * Dz * Dz], g_wqkvl[NLz * 3 * Dz * Dz];
__device__ __align__(128) __nv_bfloat16 g_wouth[NLz * Dz * Dz],     g_woutl[NLz * Dz * Dz];
__device__ __align__(128) __nv_bfloat16 g_wff1h[NLz * DFFz * Dz],   g_wff1l[NLz * DFFz * Dz];
__device__ __align__(128) __nv_bfloat16 g_wff2h[NLz * Dz * DFFz],   g_wff2l[NLz * Dz * DFFz];
__device__ __align__(128) __nv_bfloat16 g_h0h[Tz * FFDz],  g_h0l[Tz * FFDz];
__device__ __align__(128) __nv_bfloat16 g_xh[Tz * Dz],     g_xl[Tz * Dz];
__device__ __align__(128) __nv_bfloat16 g_aoh[Tz * Dz],    g_aol[Tz * Dz];
__device__ __align__(128) __nv_bfloat16 g_f1h[Tz * DFFz],  g_f1l[Tz * DFFz];
__device__ __align__(128) float g_x[Tz * Dz];
__device__ __align__(128) float g_qkv[Tz * 3 * Dz];
__device__ __align__(128) float g_obuf[Tz * Dz];
__device__ __align__(128) float g_f2[Tz * Dz];
__device__ __align__(128) float g_f2b[Tz * Dz];   // split-K second partial for ff2

// ================= fused weight fp32 -> bf16 hi/lo (all 5 weights) =================
// segment bounds (elements): fc2 131072 | qkv 393216 | out 131072 | ff1 524288 | ff2 524288
#define CE0 131072
#define CE1 524288
#define CE2 655360
#define CE3 1179648
#define CE4 1703936

__global__ __launch_bounds__(256) void convert_all_kernel(
    const float* __restrict__ fc2, const float* __restrict__ qkvw,
    const float* __restrict__ outw, const float* __restrict__ ff1,
    const float* __restrict__ ff2,
    __nv_bfloat16* __restrict__ fc2h, __nv_bfloat16* __restrict__ fc2l,
    __nv_bfloat16* __restrict__ qh,   __nv_bfloat16* __restrict__ ql,
    __nv_bfloat16* __restrict__ ohw,  __nv_bfloat16* __restrict__ olw,
    __nv_bfloat16* __restrict__ f1h,  __nv_bfloat16* __restrict__ f1l,
    __nv_bfloat16* __restrict__ f2h,  __nv_bfloat16* __restrict__ f2l)
{
    int q = blockIdx.x * 256 + threadIdx.x;
    long i = (long)q * 4;
    if (i >= CE4) return;
    const float* s; __nv_bfloat16 *hp, *lp; long off;
    if (i < CE0)      { s = fc2;  hp = fc2h; lp = fc2l; off = i; }
    else if (i < CE1) { s = qkvw; hp = qh;   lp = ql;   off = i - CE0; }
    else if (i < CE2) { s = outw; hp = ohw;  lp = olw;  off = i - CE1; }
    else if (i < CE3) { s = ff1;  hp = f1h;  lp = f1l;  off = i - CE2; }
    else              { s = ff2;  hp = f2h;  lp = f2l;  off = i - CE3; }
    float4 v = *(const float4*)(s + off);
    __nv_bfloat16 h0 = __float2bfloat16(v.x), h1 = __float2bfloat16(v.y);
    __nv_bfloat16 h2 = __float2bfloat16(v.z), h3 = __float2bfloat16(v.w);
    *(__nv_bfloat162*)(hp + off)     = __nv_bfloat162(h0, h1);
    *(__nv_bfloat162*)(hp + off + 2) = __nv_bfloat162(h2, h3);
    *(__nv_bfloat162*)(lp + off)     = __nv_bfloat162(
        __float2bfloat16(v.x - __bfloat162float(h0)),
        __float2bfloat16(v.y - __bfloat162float(h1)));
    *(__nv_bfloat162*)(lp + off + 2) = __nv_bfloat162(
        __float2bfloat16(v.z - __bfloat162float(h2)),
        __float2bfloat16(v.w - __bfloat162float(h3)));
}

// ================= embed: fixed-7 masked gather, relu, hi/lo =================
__global__ __launch_bounds__(512) void embed_kernel(
    const int* __restrict__ word, const int* __restrict__ ngram,
    const float* __restrict__ fc1w, const float* __restrict__ fc1b,
    __nv_bfloat16* __restrict__ h0h, __nv_bfloat16* __restrict__ h0l)
{
    int t = blockIdx.x;
    __shared__ int cols7[7];
    __shared__ float msk[7];
    if (threadIdx.x == 0) {
        cols7[0] = word[t];
        msk[0] = 1.f;
        #pragma unroll
        for (int k = 0; k < Kz; k++) {
            int c = WORDN + ngram[t * Kz + k];
            bool dup = false;
            for (int j = 1; j <= k; j++) if (cols7[j] == c) dup = true;
            cols7[k + 1] = c;
            msk[k + 1] = dup ? 0.f : 1.f;
        }
    }
    __syncthreads();
    int r = threadIdx.x;
    const float* row = fc1w + (size_t)r * FDIM;
    float s = fc1b[r];
    #pragma unroll
    for (int i = 0; i < 7; i++) s += msk[i] * __ldg(row + cols7[i]);
    s = fmaxf(s, 0.0f);
    __nv_bfloat16 h = __float2bfloat16(s);
    size_t o = (size_t)t * FFDz + r;
    h0h[o] = h;
    h0l[o] = __float2bfloat16(s - __bfloat162float(h));
}

// ================= split-bf16 GEMM via mma.sync m16n8k16 (cp.async pipelined) ====
// C[M,N] = (Ahi+Alo)[M,K] @ (Whi+Wlo)[N,K]^T + bias  (3-term, AloWlo dropped)
// BM=64, BN=64, BK=32, 256 threads / 8 warps, warp tile 16x32.
// Double-buffered smem, 1 sync per K chunk. Rows 80B -> conflict-free ldmatrix.
// KSPLIT>1: blockIdx.z selects K segment; z=0 -> C with bias, z>0 -> C2 without.
template<bool RELU, bool WF32, bool WBF16, int KSPLIT>
__global__ __launch_bounds__(256) void gemm_mma(
    const __nv_bfloat16* __restrict__ Ahi, const __nv_bfloat16* __restrict__ Alo,
    const __nv_bfloat16* __restrict__ Whi, const __nv_bfloat16* __restrict__ Wlo,
    const float* __restrict__ bias, float* __restrict__ C,
    __nv_bfloat16* __restrict__ Chi, __nv_bfloat16* __restrict__ Clo,
    float* __restrict__ C2, int N, int K)
{
    extern __shared__ __align__(16) char dsm[];
    constexpr uint32_t ABY  = 64 * 80u;       // one A tile (hi or lo)
    constexpr uint32_t AALL = 2 * ABY;        // hi+lo, one buffer
    constexpr uint32_t BOFF = 2 * AALL;       // B region base
    constexpr uint32_t BBY  = 64 * 80u;
    constexpr uint32_t BALL = 2 * BBY;

    uint32_t sb = smem_u32(dsm);
    int tid = threadIdx.x, lane = tid & 31, wid = tid >> 5;
    int warp_m = wid & 3, warp_n = wid >> 2;
    int m0 = blockIdx.y * 64, n0 = blockIdx.x * 64;
    int kz = (KSPLIT > 1) ? blockIdx.z : 0;

    float acc[4][4];
    #pragma unroll
    for (int ni = 0; ni < 4; ni++)
        #pragma unroll
        for (int j = 0; j < 4; j++) acc[ni][j] = 0.f;

    int nkl = (K / KSPLIT) >> 5;           // chunks in this segment
    int kc0 = kz * nkl;                    // first global chunk index

    auto load_chunk = [&](int kc, int bb) {
        size_t kb = (size_t)kc * 32;
        {
            int row = tid >> 2, ch = tid & 3;
            size_t g = (size_t)(m0 + row) * K + kb + ch * 8;
            uint32_t sa = sb + (uint32_t)bb * AALL + row * 80 + ch * 16;
            cp_async16(sa,       Ahi + g);
            cp_async16(sa + ABY, Alo + g);
        }
        {
            int row = tid >> 2, ch = tid & 3;
            size_t g = (size_t)(n0 + row) * K + kb + ch * 8;
            uint32_t sa = sb + BOFF + (uint32_t)bb * BALL + row * 80 + ch * 16;
            cp_async16(sa,       Whi + g);
            cp_async16(sa + BBY, Wlo + g);
        }
    };

    load_chunk(kc0, 0);
    CP_COMMIT();
    CP_WAIT0();
    __syncthreads();

    int bb = 0;
    for (int c = 0; c < nkl; c++) {
        if (c + 1 < nkl) { load_chunk(kc0 + c + 1, bb ^ 1); CP_COMMIT(); }

        uint32_t aB = sb + (uint32_t)bb * AALL;
        uint32_t bB = sb + BOFF + (uint32_t)bb * BALL;
        #pragma unroll
        for (int ks = 0; ks < 2; ks++) {
            uint32_t af[2][4];
            {
                uint32_t row = warp_m * 16 + (lane & 15);
                uint32_t cb  = ks * 32 + (lane >> 4) * 16;
                uint32_t off = row * 80 + cb;
                ldsm4(af[0], aB + off);
                ldsm4(af[1], aB + ABY + off);
            }
            uint32_t bf[2][2][4];
            #pragma unroll
            for (int n2 = 0; n2 < 2; n2++) {
                uint32_t nrow = warp_n * 32 + n2 * 16 + ((lane >> 4) & 1) * 8 + (lane & 7);
                uint32_t kb_  = ks * 32 + ((lane >> 3) & 1) * 16;
                uint32_t off  = nrow * 80 + kb_;
                ldsm4(bf[0][n2], bB + off);
                ldsm4(bf[1][n2], bB + BBY + off);
            }
            #pragma unroll
            for (int ni = 0; ni < 4; ni++) {
                int n2 = ni >> 1, s = (ni & 1) * 2;
                uint32_t bh[2] = {bf[0][n2][s], bf[0][n2][s + 1]};
                uint32_t bl[2] = {bf[1][n2][s], bf[1][n2][s + 1]};
                mma16816(acc[ni], af[0], bh);   // Ahi*Whi
                mma16816(acc[ni], af[1], bh);   // Alo*Whi
                mma16816(acc[ni], af[0], bl);   // Ahi*Wlo
            }
        }
        if (c + 1 < nkl) {
            CP_WAIT0();
            __syncthreads();
            bb ^= 1;
        }
    }

    // epilogue
    float* Cw = (KSPLIT > 1 && kz > 0) ? C2 : C;
    #pragma unroll
    for (int ni = 0; ni < 4; ni++) {
        int r = m0 + warp_m * 16 + (lane >> 2);
        int cc = n0 + warp_n * 32 + ni * 8 + (lane & 3) * 2;
        float b0 = 0.f, b1 = 0.f;
        if (kz == 0) { b0 = bias[cc]; b1 = bias[cc + 1]; }
        float v00 = acc[ni][0] + b0, v01 = acc[ni][1] + b1;
        float v10 = acc[ni][2] + b0, v11 = acc[ni][3] + b1;
        if (RELU) {
            v00 = fmaxf(v00, 0.f); v01 = fmaxf(v01, 0.f);
            v10 = fmaxf(v10, 0.f); v11 = fmaxf(v11, 0.f);
        }
        size_t o0 = (size_t)r * N + cc;
        size_t o1 = (size_t)(r + 8) * N + cc;
        if (WF32) {
            *(float2*)(Cw + o0) = make_float2(v00, v01);
            *(float2*)(Cw + o1) = make_float2(v10, v11);
        }
        if (WBF16) {
            __nv_bfloat16 h00 = __float2bfloat16(v00), h01 = __float2bfloat16(v01);
            __nv_bfloat16 h10 = __float2bfloat16(v10), h11 = __float2bfloat16(v11);
            *(__nv_bfloat162*)(Chi + o0) = __nv_bfloat162(h00, h01);
            *(__nv_bfloat162*)(Chi + o1) = __nv_bfloat162(h10, h11);
            *(__nv_bfloat162*)(Clo + o0) = __nv_bfloat162(
                __float2bfloat16(v00 - __bfloat162float(h00)),
                __float2bfloat16(v01 - __bfloat162float(h01)));
            *(__nv_bfloat162*)(Clo + o1) = __nv_bfloat162(
                __float2bfloat16(v10 - __bfloat162float(h10)),
                __float2bfloat16(v11 - __bfloat162float(h11)));
        }
    }
}

// ================= attention: one block per (b,h), 256 threads =================
__global__ __launch_bounds__(256) void attn_kernel(
    const float* __restrict__ qkv,
    __nv_bfloat16* __restrict__ oh, __nv_bfloat16* __restrict__ ol)
{
    int bh = blockIdx.x;
    int b = bh >> 3, h = bh & 7;
    __shared__ float Q[64][36], Ksm[64][36], V[64][36];
    __shared__ float S[64][68];
    int tid = threadIdx.x;
    const float scale = 0.17677669529663687f;  // 1/sqrt(32)

    for (int idx = tid; idx < 64 * 32; idx += 256) {
        int l = idx >> 5, j = idx & 31;
        size_t base = (size_t)(b * 64 + l) * (3 * Dz) + h * 32 + j;
        Q[l][j]   = qkv[base];
        Ksm[l][j] = qkv[base + Dz];
        V[l][j]   = qkv[base + 2 * Dz];
    }
    __syncthreads();

    int i = tid >> 2, g = tid & 3;
    float4 qr[8];
    #pragma unroll
    for (int u = 0; u < 8; u++) qr[u] = *(float4*)&Q[i][u * 4];

    float sv[16];
    #pragma unroll
    for (int t = 0; t < 16; t++) {
        int j = g + t * 4;
        float s = 0.f;
        #pragma unroll
        for (int u = 0; u < 8; u++) {
            float4 kv = *(float4*)&Ksm[j][u * 4];
            s += qr[u].x * kv.x + qr[u].y * kv.y + qr[u].z * kv.z + qr[u].w * kv.w;
        }
        sv[t] = s * scale;
    }
    float m = -1e30f;
    #pragma unroll
    for (int t = 0; t < 16; t++) m = fmaxf(m, sv[t]);
    m = fmaxf(m, __shfl_xor_sync(0xffffffffu, m, 1));
    m = fmaxf(m, __shfl_xor_sync(0xffffffffu, m, 2));
    float sum = 0.f;
    #pragma unroll
    for (int t = 0; t < 16; t++) { sv[t] = __expf(sv[t] - m); sum += sv[t]; }
    sum += __shfl_xor_sync(0xffffffffu, sum, 1);
    sum += __shfl_xor_sync(0xffffffffu, sum, 2);
    float inv = 1.f / sum;
    #pragma unroll
    for (int t = 0; t < 16; t++) S[i][g + t * 4] = sv[t] * inv;
    __syncthreads();

    int i2 = tid >> 2, d0 = (tid & 3) * 8;
    float o[8];
    #pragma unroll
    for (int u = 0; u < 8; u++) o[u] = 0.f;
    #pragma unroll 4
    for (int j = 0; j < 64; j++) {
        float s = S[i2][j];
        float4 v0 = *(float4*)&V[j][d0];
        float4 v1 = *(float4*)&V[j][d0 + 4];
        o[0] += s * v0.x; o[1] += s * v0.y; o[2] += s * v0.z; o[3] += s * v0.w;
        o[4] += s * v1.x; o[5] += s * v1.y; o[6] += s * v1.z; o[7] += s * v1.w;
    }
    size_t ob = (size_t)(b * 64 + i2) * Dz + h * 32 + d0;
    #pragma unroll
    for (int u = 0; u < 4; u++) {
        __nv_bfloat16 ha = __float2bfloat16(o[u * 2]);
        __nv_bfloat16 hb = __float2bfloat16(o[u * 2 + 1]);
        *(__nv_bfloat162*)(oh + ob + u * 2) = __nv_bfloat162(ha, hb);
        *(__nv_bfloat162*)(ol + ob + u * 2) = __nv_bfloat162(
            __float2bfloat16(o[u * 2]     - __bfloat162float(ha)),
            __float2bfloat16(o[u * 2 + 1] - __bfloat162float(hb)));
    }
}

// ================= residual add + layernorm (+ optional 2nd residual, hi/lo) =====
__global__ __launch_bounds__(256) void add_ln_kernel(
    const float* __restrict__ xin, const float* __restrict__ res,
    const float* __restrict__ res2,
    const float* __restrict__ g, const float* __restrict__ bb,
    float* __restrict__ out,
    __nv_bfloat16* __restrict__ ohi, __nv_bfloat16* __restrict__ olo)
{
    int t = blockIdx.x;
    int d = threadIdx.x;
    size_t o = (size_t)t * Dz + d;
    float v = xin[o] + res[o];
    if (res2) v += res2[o];
    float s = v, s2 = v * v;
    #pragma unroll
    for (int off = 16; off; off >>= 1) {
        s  += __shfl_xor_sync(0xffffffffu, s,  off);
        s2 += __shfl_xor_sync(0xffffffffu, s2, off);
    }
    __shared__ float ss[8], ss2[8];
    int w = d >> 5;
    if ((d & 31) == 0) { ss[w] = s; ss2[w] = s2; }
    __syncthreads();
    float ts = 0.f, ts2 = 0.f;
    #pragma unroll
    for (int i = 0; i < 8; i++) { ts += ss[i]; ts2 += ss2[i]; }
    float mean = ts * (1.f / 256.f);
    float var  = ts2 * (1.f / 256.f) - mean * mean;
    float rstd = rsqrtf(var + EPSz);
    float r = (v - mean) * rstd * g[d] + bb[d];
    out[o] = r;
    if (ohi) {
        __nv_bfloat16 h = __float2bfloat16(r);
        ohi[o] = h;
        olo[o] = __float2bfloat16(r - __bfloat162float(h));
    }
}

// ================= launch =================
extern "C" void kernel_launch(void* const* d_in, const int* in_sizes, int n_in,
                              void* d_out, int out_size)
{
    (void)in_sizes; (void)n_in; (void)out_size;
    const int*   word   = (const int*)d_in[0];
    const int*   ngram  = (const int*)d_in[1];
    const float* fc1_w  = (const float*)d_in[2];
    const float* fc1_b  = (const float*)d_in[3];
    const float* fc2_w  = (const float*)d_in[4];
    const float* fc2_b  = (const float*)d_in[5];
    const float* qkv_w  = (const float*)d_in[6];
    const float* qkv_b  = (const float*)d_in[7];
    const float* out_w  = (const float*)d_in[8];
    const float* out_b  = (const float*)d_in[9];
    const float* ln1_g  = (const float*)d_in[10];
    const float* ln1_b  = (const float*)d_in[11];
    const float* ff1_w  = (const float*)d_in[12];
    const float* ff1_b  = (const float*)d_in[13];
    const float* ff2_w  = (const float*)d_in[14];
    const float* ff2_b  = (const float*)d_in[15];
    const float* ln2_g  = (const float*)d_in[16];
    const float* ln2_b  = (const float*)d_in[17];
    float* outp = (float*)d_out;

    __nv_bfloat16 *wfc2h, *wfc2l, *wqkvh, *wqkvl, *wouth, *woutl, *wff1h, *wff1l, *wff2h, *wff2l;
    __nv_bfloat16 *h0h, *h0l, *xh, *xl, *aoh, *aol, *f1h, *f1l;
    float *x, *qkvf, *obuf, *f2, *f2b;
    cudaGetSymbolAddress((void**)&wfc2h, g_wfc2h); cudaGetSymbolAddress((void**)&wfc2l, g_wfc2l);
    cudaGetSymbolAddress((void**)&wqkvh, g_wqkvh); cudaGetSymbolAddress((void**)&wqkvl, g_wqkvl);
    cudaGetSymbolAddress((void**)&wouth, g_wouth); cudaGetSymbolAddress((void**)&woutl, g_woutl);
    cudaGetSymbolAddress((void**)&wff1h, g_wff1h); cudaGetSymbolAddress((void**)&wff1l, g_wff1l);
    cudaGetSymbolAddress((void**)&wff2h, g_wff2h); cudaGetSymbolAddress((void**)&wff2l, g_wff2l);
    cudaGetSymbolAddress((void**)&h0h, g_h0h);     cudaGetSymbolAddress((void**)&h0l, g_h0l);
    cudaGetSymbolAddress((void**)&xh, g_xh);       cudaGetSymbolAddress((void**)&xl, g_xl);
    cudaGetSymbolAddress((void**)&aoh, g_aoh);     cudaGetSymbolAddress((void**)&aol, g_aol);
    cudaGetSymbolAddress((void**)&f1h, g_f1h);     cudaGetSymbolAddress((void**)&f1l, g_f1l);
    cudaGetSymbolAddress((void**)&x, g_x);
    cudaGetSymbolAddress((void**)&qkvf, g_qkv);
    cudaGetSymbolAddress((void**)&obuf, g_obuf);
    cudaGetSymbolAddress((void**)&f2, g_f2);
    cudaGetSymbolAddress((void**)&f2b, g_f2b);

    constexpr int SMEM1 = 40960;
    cudaFuncSetAttribute(gemm_mma<false, true,  true,  1>, cudaFuncAttributeMaxDynamicSharedMemorySize, SMEM1);
    cudaFuncSetAttribute(gemm_mma<false, true,  false, 1>, cudaFuncAttributeMaxDynamicSharedMemorySize, SMEM1);
    cudaFuncSetAttribute(gemm_mma<true,  false, true,  1>, cudaFuncAttributeMaxDynamicSharedMemorySize, SMEM1);
    cudaFuncSetAttribute(gemm_mma<false, true,  false, 2>, cudaFuncAttributeMaxDynamicSharedMemorySize, SMEM1);

    // fused weight hi/lo conversion (1 launch)
    convert_all_kernel<<<CE4 / 4 / 256, 256>>>(
        fc2_w, qkv_w, out_w, ff1_w, ff2_w,
        wfc2h, wfc2l, wqkvh, wqkvl, wouth, woutl, wff1h, wff1l, wff2h, wff2l);

    // sparse embed -> relu -> h0 hi/lo  [2048, 512]
    embed_kernel<<<Tz, 512>>>(word, ngram, fc1_w, fc1_b, h0h, h0l);

    // fc2: x = h0 @ fc2_w^T + b  [2048, 256]  (fp32 + hi/lo out) — grid 4x32
    gemm_mma<false, true, true, 1><<<dim3(Dz / 64, Tz / 64), 256, SMEM1>>>(
        h0h, h0l, wfc2h, wfc2l, fc2_b, x, xh, xl, nullptr, Dz, FFDz);

    for (int i = 0; i < NLz; i++) {
        const __nv_bfloat16* qwh = wqkvh + (size_t)i * 3 * Dz * Dz;
        const __nv_bfloat16* qwl = wqkvl + (size_t)i * 3 * Dz * Dz;
        const __nv_bfloat16* owh = wouth + (size_t)i * Dz * Dz;
        const __nv_bfloat16* owl = woutl + (size_t)i * Dz * Dz;
        const __nv_bfloat16* f1wh = wff1h + (size_t)i * DFFz * Dz;
        const __nv_bfloat16* f1wl = wff1l + (size_t)i * DFFz * Dz;
        const __nv_bfloat16* f2wh = wff2h + (size_t)i * Dz * DFFz;
        const __nv_bfloat16* f2wl = wff2l + (size_t)i * Dz * DFFz;

        // qkv projection [2048, 768] — grid 12x32 (384 CTAs)
        gemm_mma<false, true, false, 1><<<dim3(3 * Dz / 64, Tz / 64), 256, SMEM1>>>(
            xh, xl, qwh, qwl, qkv_b + (size_t)i * 3 * Dz, qkvf, nullptr, nullptr, nullptr, 3 * Dz, Dz);
        // attention -> attno hi/lo
        attn_kernel<<<Bz * Hz, 256>>>(qkvf, aoh, aol);
        // out projection [2048, 256] — grid 4x32
        gemm_mma<false, true, false, 1><<<dim3(Dz / 64, Tz / 64), 256, SMEM1>>>(
            aoh, aol, owh, owl, out_b + (size_t)i * Dz, obuf, nullptr, nullptr, nullptr, Dz, Dz);
        // x = LN(x + o), fp32 + hi/lo
        add_ln_kernel<<<Tz, 256>>>(x, obuf, nullptr, ln1_g + i * Dz, ln1_b + i * Dz, x, xh, xl);
        // ff1 + relu [2048, 1024] hi/lo only — grid 16x32 (512 CTAs)
        gemm_mma<true, false, true, 1><<<dim3(DFFz / 64, Tz / 64), 256, SMEM1>>>(
            xh, xl, f1wh, f1wl, ff1_b + (size_t)i * DFFz, nullptr, f1h, f1l, nullptr, DFFz, Dz);
        // ff2 [2048, 256], K=1024 split-K=2 — grid 4x32x2 (256 CTAs)
        gemm_mma<false, true, false, 2><<<dim3(Dz / 64, Tz / 64, 2), 256, SMEM1>>>(
            f1h, f1l, f2wh, f2wl, ff2_b + (size_t)i * Dz, f2, nullptr, nullptr, f2b, Dz, DFFz);
        // x = LN(x + f2 + f2b); final layer -> d_out (fp32 only)
        bool last = (i == NLz - 1);
        add_ln_kernel<<<Tz, 256>>>(x, f2, f2b, ln2_g + i * Dz, ln2_b + i * Dz,
                                   last ? outp : x,
                                   last ? nullptr : xh, last ? nullptr : xl);
    }
}

// round 10
// speedup vs baseline: 1.9196x; 1.0079x over previous
#include <cuda_runtime.h>
#include <cuda_bf16.h>
#include <cstdint>
#include <cstddef>

// ---------------- problem dims ----------------
#define WORDN 30000
#define FDIM  80000
#define Bz 32
#define Lz 64
#define Tz 2048
#define Kz 6
#define Dz 256
#define Hz 8
#define FFDz 512
#define DFFz 1024
#define NLz 2
#define EPSz 1e-5f

__device__ __forceinline__ uint32_t smem_u32(const void* p) {
    uint32_t a;
    asm("{ .reg .u64 t; cvta.to.shared.u64 t, %1; cvt.u32.u64 %0, t; }" : "=r"(a) : "l"(p));
    return a;
}

__device__ __forceinline__ void ldsm4(uint32_t* r, uint32_t addr) {
    asm volatile("ldmatrix.sync.aligned.m8n8.x4.shared.b16 {%0,%1,%2,%3}, [%4];"
        : "=r"(r[0]), "=r"(r[1]), "=r"(r[2]), "=r"(r[3]) : "r"(addr));
}

__device__ __forceinline__ void mma16816(float* d, const uint32_t* a, const uint32_t* b) {
    asm volatile("mma.sync.aligned.m16n8k16.row.col.f32.bf16.bf16.f32 "
        "{%0,%1,%2,%3}, {%4,%5,%6,%7}, {%8,%9}, {%0,%1,%2,%3};"
        : "+f"(d[0]), "+f"(d[1]), "+f"(d[2]), "+f"(d[3])
        : "r"(a[0]), "r"(a[1]), "r"(a[2]), "r"(a[3]), "r"(b[0]), "r"(b[1]));
}

__device__ __forceinline__ void cp_async16(uint32_t saddr, const void* gptr) {
    asm volatile("cp.async.cg.shared.global [%0], [%1], 16;" :: "r"(saddr), "l"(gptr));
}
#define CP_COMMIT() asm volatile("cp.async.commit_group;" ::: "memory")
#define CP_WAIT0()  asm volatile("cp.async.wait_group 0;" ::: "memory")

// ================= scratch (no allocation allowed) =================
__device__ __align__(128) __nv_bfloat16 g_wfc2h[FFDz * Dz],         g_wfc2l[FFDz * Dz];
__device__ __align__(128) __nv_bfloat16 g_wqkvh[NLz * 3 * Dz * Dz], g_wqkvl[NLz * 3 * Dz * Dz];
__device__ __align__(128) __nv_bfloat16 g_wouth[NLz * Dz * Dz],     g_woutl[NLz * Dz * Dz];
__device__ __align__(128) __nv_bfloat16 g_wff1h[NLz * DFFz * Dz],   g_wff1l[NLz * DFFz * Dz];
__device__ __align__(128) __nv_bfloat16 g_wff2h[NLz * Dz * DFFz],   g_wff2l[NLz * Dz * DFFz];
__device__ __align__(128) __nv_bfloat16 g_h0h[Tz * FFDz],  g_h0l[Tz * FFDz];
__device__ __align__(128) __nv_bfloat16 g_xh[Tz * Dz],     g_xl[Tz * Dz];
__device__ __align__(128) __nv_bfloat16 g_aoh[Tz * Dz],    g_aol[Tz * Dz];
__device__ __align__(128) __nv_bfloat16 g_f1h[Tz * DFFz],  g_f1l[Tz * DFFz];
__device__ __align__(128) float g_x[Tz * Dz];
__device__ __align__(128) float g_qkv[Tz * 3 * Dz];
__device__ __align__(128) float g_obuf[Tz * Dz];
__device__ __align__(128) float g_obuf2[Tz * Dz];  // split-K second partial for out-proj
__device__ __align__(128) float g_f2[Tz * Dz];
__device__ __align__(128) float g_f2b[Tz * Dz];    // split-K second partial for ff2 / fc2

// ================= fused weight fp32 -> bf16 hi/lo (all 5 weights) =================
// segment bounds (elements): fc2 131072 | qkv 393216 | out 131072 | ff1 524288 | ff2 524288
#define CE0 131072
#define CE1 524288
#define CE2 655360
#define CE3 1179648
#define CE4 1703936

__global__ __launch_bounds__(256) void convert_all_kernel(
    const float* __restrict__ fc2, const float* __restrict__ qkvw,
    const float* __restrict__ outw, const float* __restrict__ ff1,
    const float* __restrict__ ff2,
    __nv_bfloat16* __restrict__ fc2h, __nv_bfloat16* __restrict__ fc2l,
    __nv_bfloat16* __restrict__ qh,   __nv_bfloat16* __restrict__ ql,
    __nv_bfloat16* __restrict__ ohw,  __nv_bfloat16* __restrict__ olw,
    __nv_bfloat16* __restrict__ f1h,  __nv_bfloat16* __restrict__ f1l,
    __nv_bfloat16* __restrict__ f2h,  __nv_bfloat16* __restrict__ f2l)
{
    int q = blockIdx.x * 256 + threadIdx.x;
    long i = (long)q * 4;
    if (i >= CE4) return;
    const float* s; __nv_bfloat16 *hp, *lp; long off;
    if (i < CE0)      { s = fc2;  hp = fc2h; lp = fc2l; off = i; }
    else if (i < CE1) { s = qkvw; hp = qh;   lp = ql;   off = i - CE0; }
    else if (i < CE2) { s = outw; hp = ohw;  lp = olw;  off = i - CE1; }
    else if (i < CE3) { s = ff1;  hp = f1h;  lp = f1l;  off = i - CE2; }
    else              { s = ff2;  hp = f2h;  lp = f2l;  off = i - CE3; }
    float4 v = *(const float4*)(s + off);
    __nv_bfloat16 h0 = __float2bfloat16(v.x), h1 = __float2bfloat16(v.y);
    __nv_bfloat16 h2 = __float2bfloat16(v.z), h3 = __float2bfloat16(v.w);
    *(__nv_bfloat162*)(hp + off)     = __nv_bfloat162(h0, h1);
    *(__nv_bfloat162*)(hp + off + 2) = __nv_bfloat162(h2, h3);
    *(__nv_bfloat162*)(lp + off)     = __nv_bfloat162(
        __float2bfloat16(v.x - __bfloat162float(h0)),
        __float2bfloat16(v.y - __bfloat162float(h1)));
    *(__nv_bfloat162*)(lp + off + 2) = __nv_bfloat162(
        __float2bfloat16(v.z - __bfloat162float(h2)),
        __float2bfloat16(v.w - __bfloat162float(h3)));
}

// ================= combine split-K partials -> f32 + hi/lo =================
__global__ __launch_bounds__(256) void combine_hilo_kernel(
    const float* __restrict__ a, const float* __restrict__ b,
    float* __restrict__ x, __nv_bfloat16* __restrict__ xh, __nv_bfloat16* __restrict__ xl)
{
    size_t i = (size_t)blockIdx.x * 256 + threadIdx.x;
    float v = a[i] + b[i];
    x[i] = v;
    __nv_bfloat16 h = __float2bfloat16(v);
    xh[i] = h;
    xl[i] = __float2bfloat16(v - __bfloat162float(h));
}

// ================= embed: fixed-7 masked gather, relu, hi/lo =================
__global__ __launch_bounds__(512) void embed_kernel(
    const int* __restrict__ word, const int* __restrict__ ngram,
    const float* __restrict__ fc1w, const float* __restrict__ fc1b,
    __nv_bfloat16* __restrict__ h0h, __nv_bfloat16* __restrict__ h0l)
{
    int t = blockIdx.x;
    __shared__ int cols7[7];
    __shared__ float msk[7];
    if (threadIdx.x == 0) {
        cols7[0] = word[t];
        msk[0] = 1.f;
        #pragma unroll
        for (int k = 0; k < Kz; k++) {
            int c = WORDN + ngram[t * Kz + k];
            bool dup = false;
            for (int j = 1; j <= k; j++) if (cols7[j] == c) dup = true;
            cols7[k + 1] = c;
            msk[k + 1] = dup ? 0.f : 1.f;
        }
    }
    __syncthreads();
    int r = threadIdx.x;
    const float* row = fc1w + (size_t)r * FDIM;
    float s = fc1b[r];
    #pragma unroll
    for (int i = 0; i < 7; i++) s += msk[i] * __ldg(row + cols7[i]);
    s = fmaxf(s, 0.0f);
    __nv_bfloat16 h = __float2bfloat16(s);
    size_t o = (size_t)t * FFDz + r;
    h0h[o] = h;
    h0l[o] = __float2bfloat16(s - __bfloat162float(h));
}

// ================= split-bf16 GEMM via mma.sync m16n8k16 (cp.async pipelined) ====
// C[M,N] = (Ahi+Alo)[M,K] @ (Whi+Wlo)[N,K]^T + bias  (3-term, AloWlo dropped)
// BM=64, BN=64, BK=32, 256 threads / 8 warps, warp tile 16x32.
// Double-buffered smem, 1 sync per K chunk. Rows 80B -> conflict-free ldmatrix.
// KSPLIT>1: blockIdx.z selects K segment; z=0 -> C with bias, z>0 -> C2 without.
template<bool RELU, bool WF32, bool WBF16, int KSPLIT>
__global__ __launch_bounds__(256) void gemm_mma(
    const __nv_bfloat16* __restrict__ Ahi, const __nv_bfloat16* __restrict__ Alo,
    const __nv_bfloat16* __restrict__ Whi, const __nv_bfloat16* __restrict__ Wlo,
    const float* __restrict__ bias, float* __restrict__ C,
    __nv_bfloat16* __restrict__ Chi, __nv_bfloat16* __restrict__ Clo,
    float* __restrict__ C2, int N, int K)
{
    extern __shared__ __align__(16) char dsm[];
    constexpr uint32_t ABY  = 64 * 80u;       // one A tile (hi or lo)
    constexpr uint32_t AALL = 2 * ABY;        // hi+lo, one buffer
    constexpr uint32_t BOFF = 2 * AALL;       // B region base
    constexpr uint32_t BBY  = 64 * 80u;
    constexpr uint32_t BALL = 2 * BBY;

    uint32_t sb = smem_u32(dsm);
    int tid = threadIdx.x, lane = tid & 31, wid = tid >> 5;
    int warp_m = wid & 3, warp_n = wid >> 2;
    int m0 = blockIdx.y * 64, n0 = blockIdx.x * 64;
    int kz = (KSPLIT > 1) ? blockIdx.z : 0;

    float acc[4][4];
    #pragma unroll
    for (int ni = 0; ni < 4; ni++)
        #pragma unroll
        for (int j = 0; j < 4; j++) acc[ni][j] = 0.f;

    int nkl = (K / KSPLIT) >> 5;           // chunks in this segment
    int kc0 = kz * nkl;                    // first global chunk index

    auto load_chunk = [&](int kc, int bb) {
        size_t kb = (size_t)kc * 32;
        {
            int row = tid >> 2, ch = tid & 3;
            size_t g = (size_t)(m0 + row) * K + kb + ch * 8;
            uint32_t sa = sb + (uint32_t)bb * AALL + row * 80 + ch * 16;
            cp_async16(sa,       Ahi + g);
            cp_async16(sa + ABY, Alo + g);
        }
        {
            int row = tid >> 2, ch = tid & 3;
            size_t g = (size_t)(n0 + row) * K + kb + ch * 8;
            uint32_t sa = sb + BOFF + (uint32_t)bb * BALL + row * 80 + ch * 16;
            cp_async16(sa,       Whi + g);
            cp_async16(sa + BBY, Wlo + g);
        }
    };

    load_chunk(kc0, 0);
    CP_COMMIT();
    CP_WAIT0();
    __syncthreads();

    int bb = 0;
    for (int c = 0; c < nkl; c++) {
        if (c + 1 < nkl) { load_chunk(kc0 + c + 1, bb ^ 1); CP_COMMIT(); }

        uint32_t aB = sb + (uint32_t)bb * AALL;
        uint32_t bB = sb + BOFF + (uint32_t)bb * BALL;

        // hoist A fragments for both k16 steps (4 independent LDSM up front)
        uint32_t afA[2][2][4];   // [ks][hi/lo][frag]
        #pragma unroll
        for (int ks = 0; ks < 2; ks++) {
            uint32_t row = warp_m * 16 + (lane & 15);
            uint32_t cb  = ks * 32 + (lane >> 4) * 16;
            uint32_t off = row * 80 + cb;
            ldsm4(afA[ks][0], aB + off);
            ldsm4(afA[ks][1], aB + ABY + off);
        }
        #pragma unroll
        for (int ks = 0; ks < 2; ks++) {
            uint32_t bf[2][2][4];
            #pragma unroll
            for (int n2 = 0; n2 < 2; n2++) {
                uint32_t nrow = warp_n * 32 + n2 * 16 + ((lane >> 4) & 1) * 8 + (lane & 7);
                uint32_t kb_  = ks * 32 + ((lane >> 3) & 1) * 16;
                uint32_t off  = nrow * 80 + kb_;
                ldsm4(bf[0][n2], bB + off);
                ldsm4(bf[1][n2], bB + BBY + off);
            }
            #pragma unroll
            for (int ni = 0; ni < 4; ni++) {
                int n2 = ni >> 1, s = (ni & 1) * 2;
                uint32_t bh[2] = {bf[0][n2][s], bf[0][n2][s + 1]};
                uint32_t bl[2] = {bf[1][n2][s], bf[1][n2][s + 1]};
                mma16816(acc[ni], afA[ks][0], bh);   // Ahi*Whi
                mma16816(acc[ni], afA[ks][1], bh);   // Alo*Whi
                mma16816(acc[ni], afA[ks][0], bl);   // Ahi*Wlo
            }
        }
        if (c + 1 < nkl) {
            CP_WAIT0();
            __syncthreads();
            bb ^= 1;
        }
    }

    // epilogue
    float* Cw = (KSPLIT > 1 && kz > 0) ? C2 : C;
    #pragma unroll
    for (int ni = 0; ni < 4; ni++) {
        int r = m0 + warp_m * 16 + (lane >> 2);
        int cc = n0 + warp_n * 32 + ni * 8 + (lane & 3) * 2;
        float b0 = 0.f, b1 = 0.f;
        if (kz == 0) { b0 = bias[cc]; b1 = bias[cc + 1]; }
        float v00 = acc[ni][0] + b0, v01 = acc[ni][1] + b1;
        float v10 = acc[ni][2] + b0, v11 = acc[ni][3] + b1;
        if (RELU) {
            v00 = fmaxf(v00, 0.f); v01 = fmaxf(v01, 0.f);
            v10 = fmaxf(v10, 0.f); v11 = fmaxf(v11, 0.f);
        }
        size_t o0 = (size_t)r * N + cc;
        size_t o1 = (size_t)(r + 8) * N + cc;
        if (WF32) {
            *(float2*)(Cw + o0) = make_float2(v00, v01);
            *(float2*)(Cw + o1) = make_float2(v10, v11);
        }
        if (WBF16) {
            __nv_bfloat16 h00 = __float2bfloat16(v00), h01 = __float2bfloat16(v01);
            __nv_bfloat16 h10 = __float2bfloat16(v10), h11 = __float2bfloat16(v11);
            *(__nv_bfloat162*)(Chi + o0) = __nv_bfloat162(h00, h01);
            *(__nv_bfloat162*)(Chi + o1) = __nv_bfloat162(h10, h11);
            *(__nv_bfloat162*)(Clo + o0) = __nv_bfloat162(
                __float2bfloat16(v00 - __bfloat162float(h00)),
                __float2bfloat16(v01 - __bfloat162float(h01)));
            *(__nv_bfloat162*)(Clo + o1) = __nv_bfloat162(
                __float2bfloat16(v10 - __bfloat162float(h10)),
                __float2bfloat16(v11 - __bfloat162float(h11)));
        }
    }
}

// ================= attention: one block per (b,h), 256 threads =================
__global__ __launch_bounds__(256) void attn_kernel(
    const float* __restrict__ qkv,
    __nv_bfloat16* __restrict__ oh, __nv_bfloat16* __restrict__ ol)
{
    int bh = blockIdx.x;
    int b = bh >> 3, h = bh & 7;
    __shared__ float Q[64][36], Ksm[64][36], V[64][36];
    __shared__ float S[64][68];
    int tid = threadIdx.x;
    const float scale = 0.17677669529663687f;  // 1/sqrt(32)

    for (int idx = tid; idx < 64 * 32; idx += 256) {
        int l = idx >> 5, j = idx & 31;
        size_t base = (size_t)(b * 64 + l) * (3 * Dz) + h * 32 + j;
        Q[l][j]   = qkv[base];
        Ksm[l][j] = qkv[base + Dz];
        V[l][j]   = qkv[base + 2 * Dz];
    }
    __syncthreads();

    int i = tid >> 2, g = tid & 3;
    float4 qr[8];
    #pragma unroll
    for (int u = 0; u < 8; u++) qr[u] = *(float4*)&Q[i][u * 4];

    float sv[16];
    #pragma unroll
    for (int t = 0; t < 16; t++) {
        int j = g + t * 4;
        float s = 0.f;
        #pragma unroll
        for (int u = 0; u < 8; u++) {
            float4 kv = *(float4*)&Ksm[j][u * 4];
            s += qr[u].x * kv.x + qr[u].y * kv.y + qr[u].z * kv.z + qr[u].w * kv.w;
        }
        sv[t] = s * scale;
    }
    float m = -1e30f;
    #pragma unroll
    for (int t = 0; t < 16; t++) m = fmaxf(m, sv[t]);
    m = fmaxf(m, __shfl_xor_sync(0xffffffffu, m, 1));
    m = fmaxf(m, __shfl_xor_sync(0xffffffffu, m, 2));
    float sum = 0.f;
    #pragma unroll
    for (int t = 0; t < 16; t++) { sv[t] = __expf(sv[t] - m); sum += sv[t]; }
    sum += __shfl_xor_sync(0xffffffffu, sum, 1);
    sum += __shfl_xor_sync(0xffffffffu, sum, 2);
    float inv = 1.f / sum;
    #pragma unroll
    for (int t = 0; t < 16; t++) S[i][g + t * 4] = sv[t] * inv;
    __syncthreads();

    int i2 = tid >> 2, d0 = (tid & 3) * 8;
    float o[8];
    #pragma unroll
    for (int u = 0; u < 8; u++) o[u] = 0.f;
    #pragma unroll 4
    for (int j = 0; j < 64; j++) {
        float s = S[i2][j];
        float4 v0 = *(float4*)&V[j][d0];
        float4 v1 = *(float4*)&V[j][d0 + 4];
        o[0] += s * v0.x; o[1] += s * v0.y; o[2] += s * v0.z; o[3] += s * v0.w;
        o[4] += s * v1.x; o[5] += s * v1.y; o[6] += s * v1.z; o[7] += s * v1.w;
    }
    size_t ob = (size_t)(b * 64 + i2) * Dz + h * 32 + d0;
    #pragma unroll
    for (int u = 0; u < 4; u++) {
        __nv_bfloat16 ha = __float2bfloat16(o[u * 2]);
        __nv_bfloat16 hb = __float2bfloat16(o[u * 2 + 1]);
        *(__nv_bfloat162*)(oh + ob + u * 2) = __nv_bfloat162(ha, hb);
        *(__nv_bfloat162*)(ol + ob + u * 2) = __nv_bfloat162(
            __float2bfloat16(o[u * 2]     - __bfloat162float(ha)),
            __float2bfloat16(o[u * 2 + 1] - __bfloat162float(hb)));
    }
}

// ================= residual add + layernorm (+ optional 2nd residual, hi/lo) =====
__global__ __launch_bounds__(256) void add_ln_kernel(
    const float* __restrict__ xin, const float* __restrict__ res,
    const float* __restrict__ res2,
    const float* __restrict__ g, const float* __restrict__ bb,
    float* __restrict__ out,
    __nv_bfloat16* __restrict__ ohi, __nv_bfloat16* __restrict__ olo)
{
    int t = blockIdx.x;
    int d = threadIdx.x;
    size_t o = (size_t)t * Dz + d;
    float v = xin[o] + res[o];
    if (res2) v += res2[o];
    float s = v, s2 = v * v;
    #pragma unroll
    for (int off = 16; off; off >>= 1) {
        s  += __shfl_xor_sync(0xffffffffu, s,  off);
        s2 += __shfl_xor_sync(0xffffffffu, s2, off);
    }
    __shared__ float ss[8], ss2[8];
    int w = d >> 5;
    if ((d & 31) == 0) { ss[w] = s; ss2[w] = s2; }
    __syncthreads();
    float ts = 0.f, ts2 = 0.f;
    #pragma unroll
    for (int i = 0; i < 8; i++) { ts += ss[i]; ts2 += ss2[i]; }
    float mean = ts * (1.f / 256.f);
    float var  = ts2 * (1.f / 256.f) - mean * mean;
    float rstd = rsqrtf(var + EPSz);
    float r = (v - mean) * rstd * g[d] + bb[d];
    out[o] = r;
    if (ohi) {
        __nv_bfloat16 h = __float2bfloat16(r);
        ohi[o] = h;
        olo[o] = __float2bfloat16(r - __bfloat162float(h));
    }
}

// ================= launch =================
extern "C" void kernel_launch(void* const* d_in, const int* in_sizes, int n_in,
                              void* d_out, int out_size)
{
    (void)in_sizes; (void)n_in; (void)out_size;
    const int*   word   = (const int*)d_in[0];
    const int*   ngram  = (const int*)d_in[1];
    const float* fc1_w  = (const float*)d_in[2];
    const float* fc1_b  = (const float*)d_in[3];
    const float* fc2_w  = (const float*)d_in[4];
    const float* fc2_b  = (const float*)d_in[5];
    const float* qkv_w  = (const float*)d_in[6];
    const float* qkv_b  = (const float*)d_in[7];
    const float* out_w  = (const float*)d_in[8];
    const float* out_b  = (const float*)d_in[9];
    const float* ln1_g  = (const float*)d_in[10];
    const float* ln1_b  = (const float*)d_in[11];
    const float* ff1_w  = (const float*)d_in[12];
    const float* ff1_b  = (const float*)d_in[13];
    const float* ff2_w  = (const float*)d_in[14];
    const float* ff2_b  = (const float*)d_in[15];
    const float* ln2_g  = (const float*)d_in[16];
    const float* ln2_b  = (const float*)d_in[17];
    float* outp = (float*)d_out;

    __nv_bfloat16 *wfc2h, *wfc2l, *wqkvh, *wqkvl, *wouth, *woutl, *wff1h, *wff1l, *wff2h, *wff2l;
    __nv_bfloat16 *h0h, *h0l, *xh, *xl, *aoh, *aol, *f1h, *f1l;
    float *x, *qkvf, *obuf, *obuf2, *f2, *f2b;
    cudaGetSymbolAddress((void**)&wfc2h, g_wfc2h); cudaGetSymbolAddress((void**)&wfc2l, g_wfc2l);
    cudaGetSymbolAddress((void**)&wqkvh, g_wqkvh); cudaGetSymbolAddress((void**)&wqkvl, g_wqkvl);
    cudaGetSymbolAddress((void**)&wouth, g_wouth); cudaGetSymbolAddress((void**)&woutl, g_woutl);
    cudaGetSymbolAddress((void**)&wff1h, g_wff1h); cudaGetSymbolAddress((void**)&wff1l, g_wff1l);
    cudaGetSymbolAddress((void**)&wff2h, g_wff2h); cudaGetSymbolAddress((void**)&wff2l, g_wff2l);
    cudaGetSymbolAddress((void**)&h0h, g_h0h);     cudaGetSymbolAddress((void**)&h0l, g_h0l);
    cudaGetSymbolAddress((void**)&xh, g_xh);       cudaGetSymbolAddress((void**)&xl, g_xl);
    cudaGetSymbolAddress((void**)&aoh, g_aoh);     cudaGetSymbolAddress((void**)&aol, g_aol);
    cudaGetSymbolAddress((void**)&f1h, g_f1h);     cudaGetSymbolAddress((void**)&f1l, g_f1l);
    cudaGetSymbolAddress((void**)&x, g_x);
    cudaGetSymbolAddress((void**)&qkvf, g_qkv);
    cudaGetSymbolAddress((void**)&obuf, g_obuf);
    cudaGetSymbolAddress((void**)&obuf2, g_obuf2);
    cudaGetSymbolAddress((void**)&f2, g_f2);
    cudaGetSymbolAddress((void**)&f2b, g_f2b);

    constexpr int SMEM1 = 40960;
    cudaFuncSetAttribute(gemm_mma<false, true,  false, 1>, cudaFuncAttributeMaxDynamicSharedMemorySize, SMEM1);
    cudaFuncSetAttribute(gemm_mma<true,  false, true,  1>, cudaFuncAttributeMaxDynamicSharedMemorySize, SMEM1);
    cudaFuncSetAttribute(gemm_mma<false, true,  false, 2>, cudaFuncAttributeMaxDynamicSharedMemorySize, SMEM1);

    // fused weight hi/lo conversion (1 launch)
    convert_all_kernel<<<CE4 / 4 / 256, 256>>>(
        fc2_w, qkv_w, out_w, ff1_w, ff2_w,
        wfc2h, wfc2l, wqkvh, wqkvl, wouth, woutl, wff1h, wff1l, wff2h, wff2l);

    // sparse embed -> relu -> h0 hi/lo  [2048, 512]
    embed_kernel<<<Tz, 512>>>(word, ngram, fc1_w, fc1_b, h0h, h0l);

    // fc2: x = h0 @ fc2_w^T + b  [2048, 256], K=512 split-K=2 — grid 4x32x2 (256 CTAs)
    gemm_mma<false, true, false, 2><<<dim3(Dz / 64, Tz / 64, 2), 256, SMEM1>>>(
        h0h, h0l, wfc2h, wfc2l, fc2_b, f2, nullptr, nullptr, f2b, Dz, FFDz);
    // combine fc2 partials -> x + hi/lo
    combine_hilo_kernel<<<(Tz * Dz) / 256, 256>>>(f2, f2b, x, xh, xl);

    for (int i = 0; i < NLz; i++) {
        const __nv_bfloat16* qwh = wqkvh + (size_t)i * 3 * Dz * Dz;
        const __nv_bfloat16* qwl = wqkvl + (size_t)i * 3 * Dz * Dz;
        const __nv_bfloat16* owh = wouth + (size_t)i * Dz * Dz;
        const __nv_bfloat16* owl = woutl + (size_t)i * Dz * Dz;
        const __nv_bfloat16* f1wh = wff1h + (size_t)i * DFFz * Dz;
        const __nv_bfloat16* f1wl = wff1l + (size_t)i * DFFz * Dz;
        const __nv_bfloat16* f2wh = wff2h + (size_t)i * Dz * DFFz;
        const __nv_bfloat16* f2wl = wff2l + (size_t)i * Dz * DFFz;

        // qkv projection [2048, 768] — grid 12x32 (384 CTAs)
        gemm_mma<false, true, false, 1><<<dim3(3 * Dz / 64, Tz / 64), 256, SMEM1>>>(
            xh, xl, qwh, qwl, qkv_b + (size_t)i * 3 * Dz, qkvf, nullptr, nullptr, nullptr, 3 * Dz, Dz);
        // attention -> attno hi/lo
        attn_kernel<<<Bz * Hz, 256>>>(qkvf, aoh, aol);
        // out projection [2048, 256], K=256 split-K=2 — grid 4x32x2 (256 CTAs)
        gemm_mma<false, true, false, 2><<<dim3(Dz / 64, Tz / 64, 2), 256, SMEM1>>>(
            aoh, aol, owh, owl, out_b + (size_t)i * Dz, obuf, nullptr, nullptr, obuf2, Dz, Dz);
        // x = LN(x + obuf + obuf2), fp32 + hi/lo
        add_ln_kernel<<<Tz, 256>>>(x, obuf, obuf2, ln1_g + i * Dz, ln1_b + i * Dz, x, xh, xl);
        // ff1 + relu [2048, 1024] hi/lo only — grid 16x32 (512 CTAs)
        gemm_mma<true, false, true, 1><<<dim3(DFFz / 64, Tz / 64), 256, SMEM1>>>(
            xh, xl, f1wh, f1wl, ff1_b + (size_t)i * DFFz, nullptr, f1h, f1l, nullptr, DFFz, Dz);
        // ff2 [2048, 256], K=1024 split-K=2 — grid 4x32x2 (256 CTAs)
        gemm_mma<false, true, false, 2><<<dim3(Dz / 64, Tz / 64, 2), 256, SMEM1>>>(
            f1h, f1l, f2wh, f2wl, ff2_b + (size_t)i * Dz, f2, nullptr, nullptr, f2b, Dz, DFFz);
        // x = LN(x + f2 + f2b); final layer -> d_out (fp32 only)
        bool last = (i == NLz - 1);
        add_ln_kernel<<<Tz, 256>>>(x, f2, f2b, ln2_g + i * Dz, ln2_b + i * Dz,
                                   last ? outp : x,
                                   last ? nullptr : xh, last ? nullptr : xl);
    }
}

// round 11
// speedup vs baseline: 1.9360x; 1.0085x over previous
#include <cuda_runtime.h>
#include <cuda_bf16.h>
#include <cstdint>
#include <cstddef>

// ---------------- problem dims ----------------
#define WORDN 30000
#define FDIM  80000
#define Bz 32
#define Lz 64
#define Tz 2048
#define Kz 6
#define Dz 256
#define Hz 8
#define FFDz 512
#define DFFz 1024
#define NLz 2
#define EPSz 1e-5f

__device__ __forceinline__ uint32_t smem_u32(const void* p) {
    uint32_t a;
    asm("{ .reg .u64 t; cvta.to.shared.u64 t, %1; cvt.u32.u64 %0, t; }" : "=r"(a) : "l"(p));
    return a;
}

__device__ __forceinline__ void ldsm4(uint32_t* r, uint32_t addr) {
    asm volatile("ldmatrix.sync.aligned.m8n8.x4.shared.b16 {%0,%1,%2,%3}, [%4];"
        : "=r"(r[0]), "=r"(r[1]), "=r"(r[2]), "=r"(r[3]) : "r"(addr));
}

__device__ __forceinline__ void mma16816(float* d, const uint32_t* a, const uint32_t* b) {
    asm volatile("mma.sync.aligned.m16n8k16.row.col.f32.bf16.bf16.f32 "
        "{%0,%1,%2,%3}, {%4,%5,%6,%7}, {%8,%9}, {%0,%1,%2,%3};"
        : "+f"(d[0]), "+f"(d[1]), "+f"(d[2]), "+f"(d[3])
        : "r"(a[0]), "r"(a[1]), "r"(a[2]), "r"(a[3]), "r"(b[0]), "r"(b[1]));
}

__device__ __forceinline__ void cp_async16(uint32_t saddr, const void* gptr) {
    asm volatile("cp.async.cg.shared.global [%0], [%1], 16;" :: "r"(saddr), "l"(gptr));
}
#define CP_COMMIT() asm volatile("cp.async.commit_group;" ::: "memory")
#define CP_WAIT0()  asm volatile("cp.async.wait_group 0;" ::: "memory")
#define CP_WAIT1()  asm volatile("cp.async.wait_group 1;" ::: "memory")

// ================= scratch (no allocation allowed) =================
__device__ __align__(128) __nv_bfloat16 g_wfc2h[FFDz * Dz],         g_wfc2l[FFDz * Dz];
__device__ __align__(128) __nv_bfloat16 g_wqkvh[NLz * 3 * Dz * Dz], g_wqkvl[NLz * 3 * Dz * Dz];
__device__ __align__(128) __nv_bfloat16 g_wouth[NLz * Dz * Dz],     g_woutl[NLz * Dz * Dz];
__device__ __align__(128) __nv_bfloat16 g_wff1h[NLz * DFFz * Dz],   g_wff1l[NLz * DFFz * Dz];
__device__ __align__(128) __nv_bfloat16 g_wff2h[NLz * Dz * DFFz],   g_wff2l[NLz * Dz * DFFz];
__device__ __align__(128) __nv_bfloat16 g_h0h[Tz * FFDz],  g_h0l[Tz * FFDz];
__device__ __align__(128) __nv_bfloat16 g_xh[Tz * Dz],     g_xl[Tz * Dz];
__device__ __align__(128) __nv_bfloat16 g_aoh[Tz * Dz],    g_aol[Tz * Dz];
__device__ __align__(128) __nv_bfloat16 g_f1h[Tz * DFFz],  g_f1l[Tz * DFFz];
__device__ __align__(128) float g_x[Tz * Dz];
__device__ __align__(128) float g_qkv[Tz * 3 * Dz];
__device__ __align__(128) float g_obuf[Tz * Dz];
__device__ __align__(128) float g_obuf2[Tz * Dz];  // split-K second partial (out-proj)
__device__ __align__(128) float g_f2[Tz * Dz];
__device__ __align__(128) float g_f2b[Tz * Dz];    // split-K second partial (ff2)

// ================= fused embed + weight-convert (one launch) =================
// blocks [0, 512):    embed — 4 tokens per block, 512 threads (one FFD row each)
// blocks [512, 1344): weight fp32 -> bf16 hi/lo, 4 elems per thread
// segment bounds (elements): fc2 131072 | qkv 393216 | out 131072 | ff1 524288 | ff2 524288
#define CE0 131072
#define CE1 524288
#define CE2 655360
#define CE3 1179648
#define CE4 1703936
#define EMB_BLKS 512
#define CVT_BLKS 832        // 832*512*4 = 1703936 = CE4

__global__ __launch_bounds__(512) void embed_convert_kernel(
    const int* __restrict__ word, const int* __restrict__ ngram,
    const float* __restrict__ fc1w, const float* __restrict__ fc1b,
    __nv_bfloat16* __restrict__ h0h, __nv_bfloat16* __restrict__ h0l,
    const float* __restrict__ fc2, const float* __restrict__ qkvw,
    const float* __restrict__ outw, const float* __restrict__ ff1,
    const float* __restrict__ ff2,
    __nv_bfloat16* __restrict__ fc2h, __nv_bfloat16* __restrict__ fc2l,
    __nv_bfloat16* __restrict__ qh,   __nv_bfloat16* __restrict__ ql,
    __nv_bfloat16* __restrict__ ohw,  __nv_bfloat16* __restrict__ olw,
    __nv_bfloat16* __restrict__ f1h,  __nv_bfloat16* __restrict__ f1l,
    __nv_bfloat16* __restrict__ f2h,  __nv_bfloat16* __restrict__ f2l)
{
    if (blockIdx.x < EMB_BLKS) {
        // ---- embed: tokens t0..t0+3 ----
        int t0 = blockIdx.x * 4;
        __shared__ int cols[4][7];
        __shared__ float msk[4][7];
        if (threadIdx.x < 4) {
            int tt = threadIdx.x;
            int t = t0 + tt;
            cols[tt][0] = word[t];
            msk[tt][0] = 1.f;
            #pragma unroll
            for (int k = 0; k < Kz; k++) {
                int c = WORDN + ngram[t * Kz + k];
                bool dup = false;
                for (int j = 1; j <= k; j++) if (cols[tt][j] == c) dup = true;
                cols[tt][k + 1] = c;
                msk[tt][k + 1] = dup ? 0.f : 1.f;
            }
        }
        __syncthreads();
        int r = threadIdx.x;
        const float* row = fc1w + (size_t)r * FDIM;
        float bias0 = fc1b[r];
        float acc[4] = {bias0, bias0, bias0, bias0};
        #pragma unroll
        for (int tt = 0; tt < 4; tt++)
            #pragma unroll
            for (int i = 0; i < 7; i++)
                acc[tt] += msk[tt][i] * __ldg(row + cols[tt][i]);
        #pragma unroll
        for (int tt = 0; tt < 4; tt++) {
            float s = fmaxf(acc[tt], 0.0f);
            __nv_bfloat16 h = __float2bfloat16(s);
            size_t o = (size_t)(t0 + tt) * FFDz + r;
            h0h[o] = h;
            h0l[o] = __float2bfloat16(s - __bfloat162float(h));
        }
    } else {
        // ---- weight convert ----
        long q = (long)(blockIdx.x - EMB_BLKS) * 512 + threadIdx.x;
        long i = q * 4;
        if (i >= CE4) return;
        const float* s; __nv_bfloat16 *hp, *lp; long off;
        if (i < CE0)      { s = fc2;  hp = fc2h; lp = fc2l; off = i; }
        else if (i < CE1) { s = qkvw; hp = qh;   lp = ql;   off = i - CE0; }
        else if (i < CE2) { s = outw; hp = ohw;  lp = olw;  off = i - CE1; }
        else if (i < CE3) { s = ff1;  hp = f1h;  lp = f1l;  off = i - CE2; }
        else              { s = ff2;  hp = f2h;  lp = f2l;  off = i - CE3; }
        float4 v = *(const float4*)(s + off);
        __nv_bfloat16 h0 = __float2bfloat16(v.x), h1 = __float2bfloat16(v.y);
        __nv_bfloat16 h2 = __float2bfloat16(v.z), h3 = __float2bfloat16(v.w);
        *(__nv_bfloat162*)(hp + off)     = __nv_bfloat162(h0, h1);
        *(__nv_bfloat162*)(hp + off + 2) = __nv_bfloat162(h2, h3);
        *(__nv_bfloat162*)(lp + off)     = __nv_bfloat162(
            __float2bfloat16(v.x - __bfloat162float(h0)),
            __float2bfloat16(v.y - __bfloat162float(h1)));
        *(__nv_bfloat162*)(lp + off + 2) = __nv_bfloat162(
            __float2bfloat16(v.z - __bfloat162float(h2)),
            __float2bfloat16(v.w - __bfloat162float(h3)));
    }
}

// ================= split-bf16 GEMM via mma.sync m16n8k16 (cp.async pipelined) ====
// C[M,N] = (Ahi+Alo)[M,K] @ (Whi+Wlo)[N,K]^T + bias  (3-term, AloWlo dropped)
// BM=64, BN=64, BK=32, 256 threads / 8 warps, warp tile 16x32.
// STAGES-deep smem pipeline (2 or 3). Rows 80B -> conflict-free ldmatrix.
// KSPLIT>1: blockIdx.z selects K segment; z=0 -> C with bias, z>0 -> C2 without.
template<bool RELU, bool WF32, bool WBF16, int KSPLIT, int STAGES>
__global__ __launch_bounds__(256) void gemm_mma(
    const __nv_bfloat16* __restrict__ Ahi, const __nv_bfloat16* __restrict__ Alo,
    const __nv_bfloat16* __restrict__ Whi, const __nv_bfloat16* __restrict__ Wlo,
    const float* __restrict__ bias, float* __restrict__ C,
    __nv_bfloat16* __restrict__ Chi, __nv_bfloat16* __restrict__ Clo,
    float* __restrict__ C2, int N, int K)
{
    extern __shared__ __align__(16) char dsm[];
    constexpr uint32_t ABY  = 64 * 80u;            // one A tile (hi or lo)
    constexpr uint32_t AALL = 2 * ABY;             // hi+lo, one stage
    constexpr uint32_t BOFF = STAGES * AALL;       // B region base
    constexpr uint32_t BBY  = 64 * 80u;
    constexpr uint32_t BALL = 2 * BBY;

    uint32_t sb = smem_u32(dsm);
    int tid = threadIdx.x, lane = tid & 31, wid = tid >> 5;
    int warp_m = wid & 3, warp_n = wid >> 2;
    int m0 = blockIdx.y * 64, n0 = blockIdx.x * 64;
    int kz = (KSPLIT > 1) ? blockIdx.z : 0;

    float acc[4][4];
    #pragma unroll
    for (int ni = 0; ni < 4; ni++)
        #pragma unroll
        for (int j = 0; j < 4; j++) acc[ni][j] = 0.f;

    int nkl = (K / KSPLIT) >> 5;
    int kc0 = kz * nkl;

    auto load_chunk = [&](int kc, int st) {
        size_t kb = (size_t)kc * 32;
        {
            int row = tid >> 2, ch = tid & 3;
            size_t g = (size_t)(m0 + row) * K + kb + ch * 8;
            uint32_t sa = sb + (uint32_t)st * AALL + row * 80 + ch * 16;
            cp_async16(sa,       Ahi + g);
            cp_async16(sa + ABY, Alo + g);
        }
        {
            int row = tid >> 2, ch = tid & 3;
            size_t g = (size_t)(n0 + row) * K + kb + ch * 8;
            uint32_t sa = sb + BOFF + (uint32_t)st * BALL + row * 80 + ch * 16;
            cp_async16(sa,       Whi + g);
            cp_async16(sa + BBY, Wlo + g);
        }
    };

    auto compute_chunk = [&](int st) {
        uint32_t aB = sb + (uint32_t)st * AALL;
        uint32_t bB = sb + BOFF + (uint32_t)st * BALL;
        uint32_t afA[2][2][4];   // [ks][hi/lo][frag]
        #pragma unroll
        for (int ks = 0; ks < 2; ks++) {
            uint32_t row = warp_m * 16 + (lane & 15);
            uint32_t cb  = ks * 32 + (lane >> 4) * 16;
            uint32_t off = row * 80 + cb;
            ldsm4(afA[ks][0], aB + off);
            ldsm4(afA[ks][1], aB + ABY + off);
        }
        #pragma unroll
        for (int ks = 0; ks < 2; ks++) {
            uint32_t bf[2][2][4];
            #pragma unroll
            for (int n2 = 0; n2 < 2; n2++) {
                uint32_t nrow = warp_n * 32 + n2 * 16 + ((lane >> 4) & 1) * 8 + (lane & 7);
                uint32_t kb_  = ks * 32 + ((lane >> 3) & 1) * 16;
                uint32_t off  = nrow * 80 + kb_;
                ldsm4(bf[0][n2], bB + off);
                ldsm4(bf[1][n2], bB + BBY + off);
            }
            #pragma unroll
            for (int ni = 0; ni < 4; ni++) {
                int n2 = ni >> 1, s = (ni & 1) * 2;
                uint32_t bh[2] = {bf[0][n2][s], bf[0][n2][s + 1]};
                uint32_t bl[2] = {bf[1][n2][s], bf[1][n2][s + 1]};
                mma16816(acc[ni], afA[ks][0], bh);   // Ahi*Whi
                mma16816(acc[ni], afA[ks][1], bh);   // Alo*Whi
                mma16816(acc[ni], afA[ks][0], bl);   // Ahi*Wlo
            }
        }
    };

    if (STAGES == 3) {
        load_chunk(kc0, 0);
        CP_COMMIT();
        if (nkl > 1) { load_chunk(kc0 + 1, 1); CP_COMMIT(); CP_WAIT1(); }
        else CP_WAIT0();
        __syncthreads();
        for (int c = 0; c < nkl; c++) {
            if (c + 2 < nkl) { load_chunk(kc0 + c + 2, (c + 2) % 3); CP_COMMIT(); }
            compute_chunk(c % 3);
            if (c + 1 < nkl) {
                if (c + 2 < nkl) CP_WAIT1(); else CP_WAIT0();
                __syncthreads();
            }
        }
    } else {
        load_chunk(kc0, 0);
        CP_COMMIT();
        CP_WAIT0();
        __syncthreads();
        for (int c = 0; c < nkl; c++) {
            if (c + 1 < nkl) { load_chunk(kc0 + c + 1, (c + 1) & 1); CP_COMMIT(); }
            compute_chunk(c & 1);
            if (c + 1 < nkl) { CP_WAIT0(); __syncthreads(); }
        }
    }

    // epilogue
    float* Cw = (KSPLIT > 1 && kz > 0) ? C2 : C;
    #pragma unroll
    for (int ni = 0; ni < 4; ni++) {
        int r = m0 + warp_m * 16 + (lane >> 2);
        int cc = n0 + warp_n * 32 + ni * 8 + (lane & 3) * 2;
        float b0 = 0.f, b1 = 0.f;
        if (kz == 0) { b0 = bias[cc]; b1 = bias[cc + 1]; }
        float v00 = acc[ni][0] + b0, v01 = acc[ni][1] + b1;
        float v10 = acc[ni][2] + b0, v11 = acc[ni][3] + b1;
        if (RELU) {
            v00 = fmaxf(v00, 0.f); v01 = fmaxf(v01, 0.f);
            v10 = fmaxf(v10, 0.f); v11 = fmaxf(v11, 0.f);
        }
        size_t o0 = (size_t)r * N + cc;
        size_t o1 = (size_t)(r + 8) * N + cc;
        if (WF32) {
            *(float2*)(Cw + o0) = make_float2(v00, v01);
            *(float2*)(Cw + o1) = make_float2(v10, v11);
        }
        if (WBF16) {
            __nv_bfloat16 h00 = __float2bfloat16(v00), h01 = __float2bfloat16(v01);
            __nv_bfloat16 h10 = __float2bfloat16(v10), h11 = __float2bfloat16(v11);
            *(__nv_bfloat162*)(Chi + o0) = __nv_bfloat162(h00, h01);
            *(__nv_bfloat162*)(Chi + o1) = __nv_bfloat162(h10, h11);
            *(__nv_bfloat162*)(Clo + o0) = __nv_bfloat162(
                __float2bfloat16(v00 - __bfloat162float(h00)),
                __float2bfloat16(v01 - __bfloat162float(h01)));
            *(__nv_bfloat162*)(Clo + o1) = __nv_bfloat162(
                __float2bfloat16(v10 - __bfloat162float(h10)),
                __float2bfloat16(v11 - __bfloat162float(h11)));
        }
    }
}

// ================= attention: one block per (b,h), 256 threads =================
__global__ __launch_bounds__(256) void attn_kernel(
    const float* __restrict__ qkv,
    __nv_bfloat16* __restrict__ oh, __nv_bfloat16* __restrict__ ol)
{
    int bh = blockIdx.x;
    int b = bh >> 3, h = bh & 7;
    __shared__ float Q[64][36], Ksm[64][36], V[64][36];
    __shared__ float S[64][68];
    int tid = threadIdx.x;
    const float scale = 0.17677669529663687f;  // 1/sqrt(32)

    for (int idx = tid; idx < 64 * 32; idx += 256) {
        int l = idx >> 5, j = idx & 31;
        size_t base = (size_t)(b * 64 + l) * (3 * Dz) + h * 32 + j;
        Q[l][j]   = qkv[base];
        Ksm[l][j] = qkv[base + Dz];
        V[l][j]   = qkv[base + 2 * Dz];
    }
    __syncthreads();

    int i = tid >> 2, g = tid & 3;
    float4 qr[8];
    #pragma unroll
    for (int u = 0; u < 8; u++) qr[u] = *(float4*)&Q[i][u * 4];

    float sv[16];
    #pragma unroll
    for (int t = 0; t < 16; t++) {
        int j = g + t * 4;
        float s = 0.f;
        #pragma unroll
        for (int u = 0; u < 8; u++) {
            float4 kv = *(float4*)&Ksm[j][u * 4];
            s += qr[u].x * kv.x + qr[u].y * kv.y + qr[u].z * kv.z + qr[u].w * kv.w;
        }
        sv[t] = s * scale;
    }
    float m = -1e30f;
    #pragma unroll
    for (int t = 0; t < 16; t++) m = fmaxf(m, sv[t]);
    m = fmaxf(m, __shfl_xor_sync(0xffffffffu, m, 1));
    m = fmaxf(m, __shfl_xor_sync(0xffffffffu, m, 2));
    float sum = 0.f;
    #pragma unroll
    for (int t = 0; t < 16; t++) { sv[t] = __expf(sv[t] - m); sum += sv[t]; }
    sum += __shfl_xor_sync(0xffffffffu, sum, 1);
    sum += __shfl_xor_sync(0xffffffffu, sum, 2);
    float inv = 1.f / sum;
    #pragma unroll
    for (int t = 0; t < 16; t++) S[i][g + t * 4] = sv[t] * inv;
    __syncthreads();

    int i2 = tid >> 2, d0 = (tid & 3) * 8;
    float o[8];
    #pragma unroll
    for (int u = 0; u < 8; u++) o[u] = 0.f;
    #pragma unroll 4
    for (int j = 0; j < 64; j++) {
        float s = S[i2][j];
        float4 v0 = *(float4*)&V[j][d0];
        float4 v1 = *(float4*)&V[j][d0 + 4];
        o[0] += s * v0.x; o[1] += s * v0.y; o[2] += s * v0.z; o[3] += s * v0.w;
        o[4] += s * v1.x; o[5] += s * v1.y; o[6] += s * v1.z; o[7] += s * v1.w;
    }
    size_t ob = (size_t)(b * 64 + i2) * Dz + h * 32 + d0;
    #pragma unroll
    for (int u = 0; u < 4; u++) {
        __nv_bfloat16 ha = __float2bfloat16(o[u * 2]);
        __nv_bfloat16 hb = __float2bfloat16(o[u * 2 + 1]);
        *(__nv_bfloat162*)(oh + ob + u * 2) = __nv_bfloat162(ha, hb);
        *(__nv_bfloat162*)(ol + ob + u * 2) = __nv_bfloat162(
            __float2bfloat16(o[u * 2]     - __bfloat162float(ha)),
            __float2bfloat16(o[u * 2 + 1] - __bfloat162float(hb)));
    }
}

// ================= residual add + layernorm (+ optional 2nd residual, hi/lo) =====
__global__ __launch_bounds__(256) void add_ln_kernel(
    const float* __restrict__ xin, const float* __restrict__ res,
    const float* __restrict__ res2,
    const float* __restrict__ g, const float* __restrict__ bb,
    float* __restrict__ out,
    __nv_bfloat16* __restrict__ ohi, __nv_bfloat16* __restrict__ olo)
{
    int t = blockIdx.x;
    int d = threadIdx.x;
    size_t o = (size_t)t * Dz + d;
    float v = xin[o] + res[o];
    if (res2) v += res2[o];
    float s = v, s2 = v * v;
    #pragma unroll
    for (int off = 16; off; off >>= 1) {
        s  += __shfl_xor_sync(0xffffffffu, s,  off);
        s2 += __shfl_xor_sync(0xffffffffu, s2, off);
    }
    __shared__ float ss[8], ss2[8];
    int w = d >> 5;
    if ((d & 31) == 0) { ss[w] = s; ss2[w] = s2; }
    __syncthreads();
    float ts = 0.f, ts2 = 0.f;
    #pragma unroll
    for (int i = 0; i < 8; i++) { ts += ss[i]; ts2 += ss2[i]; }
    float mean = ts * (1.f / 256.f);
    float var  = ts2 * (1.f / 256.f) - mean * mean;
    float rstd = rsqrtf(var + EPSz);
    float r = (v - mean) * rstd * g[d] + bb[d];
    out[o] = r;
    if (ohi) {
        __nv_bfloat16 h = __float2bfloat16(r);
        ohi[o] = h;
        olo[o] = __float2bfloat16(r - __bfloat162float(h));
    }
}

// ================= launch =================
extern "C" void kernel_launch(void* const* d_in, const int* in_sizes, int n_in,
                              void* d_out, int out_size)
{
    (void)in_sizes; (void)n_in; (void)out_size;
    const int*   word   = (const int*)d_in[0];
    const int*   ngram  = (const int*)d_in[1];
    const float* fc1_w  = (const float*)d_in[2];
    const float* fc1_b  = (const float*)d_in[3];
    const float* fc2_w  = (const float*)d_in[4];
    const float* fc2_b  = (const float*)d_in[5];
    const float* qkv_w  = (const float*)d_in[6];
    const float* qkv_b  = (const float*)d_in[7];
    const float* out_w  = (const float*)d_in[8];
    const float* out_b  = (const float*)d_in[9];
    const float* ln1_g  = (const float*)d_in[10];
    const float* ln1_b  = (const float*)d_in[11];
    const float* ff1_w  = (const float*)d_in[12];
    const float* ff1_b  = (const float*)d_in[13];
    const float* ff2_w  = (const float*)d_in[14];
    const float* ff2_b  = (const float*)d_in[15];
    const float* ln2_g  = (const float*)d_in[16];
    const float* ln2_b  = (const float*)d_in[17];
    float* outp = (float*)d_out;

    __nv_bfloat16 *wfc2h, *wfc2l, *wqkvh, *wqkvl, *wouth, *woutl, *wff1h, *wff1l, *wff2h, *wff2l;
    __nv_bfloat16 *h0h, *h0l, *xh, *xl, *aoh, *aol, *f1h, *f1l;
    float *x, *qkvf, *obuf, *obuf2, *f2, *f2b;
    cudaGetSymbolAddress((void**)&wfc2h, g_wfc2h); cudaGetSymbolAddress((void**)&wfc2l, g_wfc2l);
    cudaGetSymbolAddress((void**)&wqkvh, g_wqkvh); cudaGetSymbolAddress((void**)&wqkvl, g_wqkvl);
    cudaGetSymbolAddress((void**)&wouth, g_wouth); cudaGetSymbolAddress((void**)&woutl, g_woutl);
    cudaGetSymbolAddress((void**)&wff1h, g_wff1h); cudaGetSymbolAddress((void**)&wff1l, g_wff1l);
    cudaGetSymbolAddress((void**)&wff2h, g_wff2h); cudaGetSymbolAddress((void**)&wff2l, g_wff2l);
    cudaGetSymbolAddress((void**)&h0h, g_h0h);     cudaGetSymbolAddress((void**)&h0l, g_h0l);
    cudaGetSymbolAddress((void**)&xh, g_xh);       cudaGetSymbolAddress((void**)&xl, g_xl);
    cudaGetSymbolAddress((void**)&aoh, g_aoh);     cudaGetSymbolAddress((void**)&aol, g_aol);
    cudaGetSymbolAddress((void**)&f1h, g_f1h);     cudaGetSymbolAddress((void**)&f1l, g_f1l);
    cudaGetSymbolAddress((void**)&x, g_x);
    cudaGetSymbolAddress((void**)&qkvf, g_qkv);
    cudaGetSymbolAddress((void**)&obuf, g_obuf);
    cudaGetSymbolAddress((void**)&obuf2, g_obuf2);
    cudaGetSymbolAddress((void**)&f2, g_f2);
    cudaGetSymbolAddress((void**)&f2b, g_f2b);

    constexpr int SMEM2ST = 40960, SMEM3ST = 61440;
    cudaFuncSetAttribute(gemm_mma<false, true,  true,  1, 3>, cudaFuncAttributeMaxDynamicSharedMemorySize, SMEM3ST);
    cudaFuncSetAttribute(gemm_mma<false, true,  false, 1, 3>, cudaFuncAttributeMaxDynamicSharedMemorySize, SMEM3ST);
    cudaFuncSetAttribute(gemm_mma<false, true,  false, 2, 3>, cudaFuncAttributeMaxDynamicSharedMemorySize, SMEM3ST);
    cudaFuncSetAttribute(gemm_mma<true,  false, true,  1, 2>, cudaFuncAttributeMaxDynamicSharedMemorySize, SMEM2ST);

    // fused embed (4 tok/block) + weight hi/lo convert — one launch
    embed_convert_kernel<<<EMB_BLKS + CVT_BLKS, 512>>>(
        word, ngram, fc1_w, fc1_b, h0h, h0l,
        fc2_w, qkv_w, out_w, ff1_w, ff2_w,
        wfc2h, wfc2l, wqkvh, wqkvl, wouth, woutl, wff1h, wff1l, wff2h, wff2l);

    // fc2: x = h0 @ fc2_w^T + b  [2048, 256]  (fp32 + hi/lo out) — grid 4x32, 3-stage
    gemm_mma<false, true, true, 1, 3><<<dim3(Dz / 64, Tz / 64), 256, SMEM3ST>>>(
        h0h, h0l, wfc2h, wfc2l, fc2_b, x, xh, xl, nullptr, Dz, FFDz);

    for (int i = 0; i < NLz; i++) {
        const __nv_bfloat16* qwh = wqkvh + (size_t)i * 3 * Dz * Dz;
        const __nv_bfloat16* qwl = wqkvl + (size_t)i * 3 * Dz * Dz;
        const __nv_bfloat16* owh = wouth + (size_t)i * Dz * Dz;
        const __nv_bfloat16* owl = woutl + (size_t)i * Dz * Dz;
        const __nv_bfloat16* f1wh = wff1h + (size_t)i * DFFz * Dz;
        const __nv_bfloat16* f1wl = wff1l + (size_t)i * DFFz * Dz;
        const __nv_bfloat16* f2wh = wff2h + (size_t)i * Dz * DFFz;
        const __nv_bfloat16* f2wl = wff2l + (size_t)i * Dz * DFFz;

        // qkv projection [2048, 768] — grid 12x32 (384 CTAs), 3-stage
        gemm_mma<false, true, false, 1, 3><<<dim3(3 * Dz / 64, Tz / 64), 256, SMEM3ST>>>(
            xh, xl, qwh, qwl, qkv_b + (size_t)i * 3 * Dz, qkvf, nullptr, nullptr, nullptr, 3 * Dz, Dz);
        // attention -> attno hi/lo
        attn_kernel<<<Bz * Hz, 256>>>(qkvf, aoh, aol);
        // out projection [2048, 256], K=256 split-K=2 — grid 4x32x2 (256 CTAs), 3-stage
        gemm_mma<false, true, false, 2, 3><<<dim3(Dz / 64, Tz / 64, 2), 256, SMEM3ST>>>(
            aoh, aol, owh, owl, out_b + (size_t)i * Dz, obuf, nullptr, nullptr, obuf2, Dz, Dz);
        // x = LN(x + obuf + obuf2), fp32 + hi/lo
        add_ln_kernel<<<Tz, 256>>>(x, obuf, obuf2, ln1_g + i * Dz, ln1_b + i * Dz, x, xh, xl);
        // ff1 + relu [2048, 1024] hi/lo only — grid 16x32 (512 CTAs), 2-stage (keep occupancy)
        gemm_mma<true, false, true, 1, 2><<<dim3(DFFz / 64, Tz / 64), 256, SMEM2ST>>>(
            xh, xl, f1wh, f1wl, ff1_b + (size_t)i * DFFz, nullptr, f1h, f1l, nullptr, DFFz, Dz);
        // ff2 [2048, 256], K=1024 split-K=2 — grid 4x32x2 (256 CTAs), 3-stage
        gemm_mma<false, true, false, 2, 3><<<dim3(Dz / 64, Tz / 64, 2), 256, SMEM3ST>>>(
            f1h, f1l, f2wh, f2wl, ff2_b + (size_t)i * Dz, f2, nullptr, nullptr, f2b, Dz, DFFz);
        // x = LN(x + f2 + f2b); final layer -> d_out (fp32 only)
        bool last = (i == NLz - 1);
        add_ln_kernel<<<Tz, 256>>>(x, f2, f2b, ln2_g + i * Dz, ln2_b + i * Dz,
                                   last ? outp : x,
                                   last ? nullptr : xh, last ? nullptr : xl);
    }
}